// round 6
// baseline (speedup 1.0000x reference)
#include <cuda_runtime.h>
#include <cuda_bf16.h>
#include <math.h>
#include <stdint.h>

#define S_LEN 2048
#define DM    1024
#define NH    16
#define HD    64
#define BATCH 2
#define BHN   (BATCH * NH)        // 32
#define MROWS (BATCH * S_LEN)     // 4096
#define KCAT  3072                // 3 x DM (hi,hi,lo | hi,lo,hi)
#define NKCH  (KCAT / 64)         // 48
#define KQK   192                 // 3 x HD

// ---------------- scratch (__device__ globals) ------------------------------
__device__ __nv_bfloat16 g_Xcat[(size_t)MROWS * KCAT];
__device__ __nv_bfloat16 g_Acat[(size_t)MROWS * KCAT];
__device__ __nv_bfloat16 g_Wqc[(size_t)DM * KCAT];
__device__ __nv_bfloat16 g_Wkc[(size_t)DM * KCAT];
__device__ __nv_bfloat16 g_Wvc[(size_t)DM * KCAT];
__device__ __nv_bfloat16 g_Woc[(size_t)DM * KCAT];
__device__ __nv_bfloat16 g_Qc[(size_t)BHN * S_LEN * KQK];   // [hi,hi,lo]
__device__ __nv_bfloat16 g_Kc[(size_t)BHN * S_LEN * KQK];   // [hi,lo,hi]
__device__ __nv_bfloat16 g_Vth[(size_t)BHN * HD * S_LEN];   // V^T hi
__device__ __nv_bfloat16 g_Vtl[(size_t)BHN * HD * S_LEN];   // V^T lo

// ---------------- helpers ---------------------------------------------------
__device__ __forceinline__ uint32_t smem_u32(const void* p) {
    uint32_t a;
    asm("{ .reg .u64 t; cvta.to.shared.u64 t, %1; cvt.u32.u64 %0, t; }"
        : "=r"(a) : "l"(p));
    return a;
}
#define SW128(o) ((o) ^ (((o) >> 3) & 0x70))

__device__ __forceinline__ void ldm_x4(uint32_t* r, uint32_t addr) {
    asm volatile("ldmatrix.sync.aligned.m8n8.x4.shared.b16 {%0,%1,%2,%3}, [%4];"
                 : "=r"(r[0]), "=r"(r[1]), "=r"(r[2]), "=r"(r[3]) : "r"(addr));
}
__device__ __forceinline__ void mma_bf16(float* c, const uint32_t* a,
                                         uint32_t b0, uint32_t b1) {
    asm volatile(
        "mma.sync.aligned.m16n8k16.row.col.f32.bf16.bf16.f32 "
        "{%0,%1,%2,%3}, {%4,%5,%6,%7}, {%8,%9}, {%0,%1,%2,%3};"
        : "+f"(c[0]), "+f"(c[1]), "+f"(c[2]), "+f"(c[3])
        : "r"(a[0]), "r"(a[1]), "r"(a[2]), "r"(a[3]), "r"(b0), "r"(b1));
}
#define CP16(dst, src) \
    asm volatile("cp.async.cg.shared.global [%0], [%1], 16;" :: "r"(dst), "l"(src))
#define CP_COMMIT() asm volatile("cp.async.commit_group;")

// ---------------------------------------------------------------------------
// fp32 -> bf16 split-concat.  mode 0 (A): [hi,hi,lo]   mode 1 (B): [hi,lo,hi]
// ---------------------------------------------------------------------------
__global__ __launch_bounds__(256) void convert_cat(
    const float* __restrict__ src, __nv_bfloat16* __restrict__ dst,
    int rows, int mode)
{
    int n = rows * (DM / 4);
    for (int i = blockIdx.x * blockDim.x + threadIdx.x; i < n;
         i += gridDim.x * blockDim.x) {
        int r = i / (DM / 4), cq = i - r * (DM / 4);
        float4 v = *(const float4*)&src[(size_t)r * DM + cq * 4];
        float f[4] = {v.x, v.y, v.z, v.w};
        __nv_bfloat16 hi[4], lo[4];
#pragma unroll
        for (int j = 0; j < 4; j++) {
            hi[j] = __float2bfloat16(f[j]);
            lo[j] = __float2bfloat16(f[j] - __bfloat162float(hi[j]));
        }
        __nv_bfloat162 h01 = __halves2bfloat162(hi[0], hi[1]);
        __nv_bfloat162 h23 = __halves2bfloat162(hi[2], hi[3]);
        __nv_bfloat162 l01 = __halves2bfloat162(lo[0], lo[1]);
        __nv_bfloat162 l23 = __halves2bfloat162(lo[2], lo[3]);
        size_t base = (size_t)r * KCAT + cq * 4;
        __nv_bfloat162* d0 = (__nv_bfloat162*)&dst[base];
        __nv_bfloat162* d1 = (__nv_bfloat162*)&dst[base + DM];
        __nv_bfloat162* d2 = (__nv_bfloat162*)&dst[base + 2 * DM];
        d0[0] = h01; d0[1] = h23;
        if (mode == 0) { d1[0] = h01; d1[1] = h23; d2[0] = l01; d2[1] = l23; }
        else           { d1[0] = l01; d1[1] = l23; d2[0] = h01; d2[1] = h23; }
    }
}

// ---------------------------------------------------------------------------
// mma.sync bf16 GEMM: C[r,c] = sum_k A[r,k]*B[c,k] + bias[c]
// omode 0: fp32 row-major.  1: Q split A-layout.  2: K split B-layout.
// omode 3: V transposed hi/lo planes.
// ---------------------------------------------------------------------------
#define GEMM_SMEM 65536

__global__ __launch_bounds__(256) void gemm_mma(
    const __nv_bfloat16* __restrict__ A, const __nv_bfloat16* __restrict__ B,
    const float* __restrict__ bias, float* __restrict__ outf,
    __nv_bfloat16* __restrict__ ob1, __nv_bfloat16* __restrict__ ob2, int omode)
{
    extern __shared__ __align__(1024) char smem[];
    const int tid = threadIdx.x;
    const int wid = tid >> 5, lane = tid & 31;
    const int warp_m = wid >> 2;
    const int warp_n = wid & 3;
    const uint32_t sb = smem_u32(smem);

    const int r0 = blockIdx.y * 128, c0 = blockIdx.x * 128;
    const int ls = tid & 7;
    const int lr = tid >> 3;

#define LOAD_STAGE(chunk, stage) do {                                          \
        uint32_t ab = sb + (stage) * 16384;                                    \
        uint32_t bb = sb + 32768 + (stage) * 16384;                            \
        size_t kb = (size_t)(chunk) * 64 + ls * 8;                             \
        _Pragma("unroll")                                                      \
        for (int i_ = 0; i_ < 4; i_++) {                                       \
            int r_ = lr + 32 * i_;                                             \
            uint32_t off = SW128(r_ * 128 + ls * 16);                          \
            CP16(ab + off, &A[(size_t)(r0 + r_) * KCAT + kb]);                 \
            CP16(bb + off, &B[(size_t)(c0 + r_) * KCAT + kb]);                 \
        }                                                                      \
        CP_COMMIT();                                                           \
    } while (0)

    float acc[4][4][4] = {};
    LOAD_STAGE(0, 0);

    for (int c = 0; c < NKCH; c++) {
        const int st = c & 1;
        if (c + 1 < NKCH) {
            LOAD_STAGE(c + 1, st ^ 1);
            asm volatile("cp.async.wait_group 1;");
        } else {
            asm volatile("cp.async.wait_group 0;");
        }
        __syncthreads();

        const uint32_t abase = sb + st * 16384;
        const uint32_t bbase = sb + 32768 + st * 16384;
#pragma unroll
        for (int ks = 0; ks < 4; ks++) {
            uint32_t af[4][4];
#pragma unroll
            for (int mt = 0; mt < 4; mt++) {
                int row = warp_m * 64 + mt * 16 + (lane & 15);
                int seg = ks * 2 + (lane >> 4);
                ldm_x4(af[mt], abase + SW128(row * 128 + seg * 16));
            }
            uint32_t bf[2][4];
#pragma unroll
            for (int h = 0; h < 2; h++) {
                int row = warp_n * 32 + h * 16 + ((lane >> 4) & 1) * 8 + (lane & 7);
                int seg = ks * 2 + ((lane >> 3) & 1);
                ldm_x4(bf[h], bbase + SW128(row * 128 + seg * 16));
            }
#pragma unroll
            for (int mt = 0; mt < 4; mt++)
#pragma unroll
                for (int nt = 0; nt < 4; nt++)
                    mma_bf16(acc[mt][nt], af[mt],
                             bf[nt >> 1][(nt & 1) * 2], bf[nt >> 1][(nt & 1) * 2 + 1]);
        }
        __syncthreads();
    }
#undef LOAD_STAGE

    const int mrow = lane >> 2;
    const int ncol = 2 * (lane & 3);
#pragma unroll
    for (int mt = 0; mt < 4; mt++) {
#pragma unroll
        for (int nt = 0; nt < 4; nt++) {
            int cg = c0 + warp_n * 32 + nt * 8 + ncol;
            float b0 = __ldg(&bias[cg]), b1 = __ldg(&bias[cg + 1]);
#pragma unroll
            for (int half = 0; half < 2; half++) {
                int r = r0 + warp_m * 64 + mt * 16 + mrow + half * 8;
                float v0 = acc[mt][nt][half * 2] + b0;
                float v1 = acc[mt][nt][half * 2 + 1] + b1;
                if (omode == 0) {
                    float2 v = {v0, v1};
                    *(float2*)&outf[(size_t)r * DM + cg] = v;
                } else {
                    int bb = r >> 11, s = r & (S_LEN - 1);
                    int h = cg >> 6, hd = cg & 63;
                    __nv_bfloat16 h0 = __float2bfloat16(v0);
                    __nv_bfloat16 h1 = __float2bfloat16(v1);
                    __nv_bfloat16 l0 = __float2bfloat16(v0 - __bfloat162float(h0));
                    __nv_bfloat16 l1 = __float2bfloat16(v1 - __bfloat162float(h1));
                    __nv_bfloat162 hh = __halves2bfloat162(h0, h1);
                    __nv_bfloat162 ll = __halves2bfloat162(l0, l1);
                    if (omode == 3) {
                        size_t pb = ((size_t)(bb * NH + h) * HD + hd) * S_LEN + s;
                        ob1[pb] = h0; ob1[pb + S_LEN] = h1;
                        ob2[pb] = l0; ob2[pb + S_LEN] = l1;
                    } else {
                        size_t base = ((size_t)(bb * NH + h) * S_LEN + s) * KQK + hd;
                        *(__nv_bfloat162*)&ob1[base] = hh;
                        if (omode == 1) {
                            *(__nv_bfloat162*)&ob1[base + HD] = hh;
                            *(__nv_bfloat162*)&ob1[base + 2 * HD] = ll;
                        } else {
                            *(__nv_bfloat162*)&ob1[base + HD] = ll;
                            *(__nv_bfloat162*)&ob1[base + 2 * HD] = hh;
                        }
                    }
                }
            }
        }
    }
}

// ---------------------------------------------------------------------------
// scores_mma: attn[bh,q,k] = 0.125 * sum Q*K  via bf16 split (K'=192)
// ---------------------------------------------------------------------------
#define SC_SMEM 65536

__global__ __launch_bounds__(256) void scores_mma(
    const __nv_bfloat16* __restrict__ Qc, const __nv_bfloat16* __restrict__ Kc,
    float* __restrict__ attn)
{
    const int kt = blockIdx.x, qt = blockIdx.y, bh = blockIdx.z;
    if (kt > qt) return;
    extern __shared__ __align__(1024) char smem[];
    const int tid = threadIdx.x;
    const int wid = tid >> 5, lane = tid & 31;
    const int warp_m = wid >> 2;
    const int warp_n = wid & 3;
    const uint32_t sb = smem_u32(smem);
    const int q0 = qt * 128, c0 = kt * 128;

    const __nv_bfloat16* Ab = Qc + (size_t)bh * S_LEN * KQK;
    const __nv_bfloat16* Bb = Kc + (size_t)bh * S_LEN * KQK;
    const int ls = tid & 7;
    const int lr = tid >> 3;

#define SC_LOAD(chunk, stage) do {                                             \
        uint32_t ab = sb + (stage) * 16384;                                    \
        uint32_t bb = sb + 32768 + (stage) * 16384;                            \
        size_t kb = (size_t)(chunk) * 64 + ls * 8;                             \
        _Pragma("unroll")                                                      \
        for (int i_ = 0; i_ < 4; i_++) {                                       \
            int r_ = lr + 32 * i_;                                             \
            uint32_t off = SW128(r_ * 128 + ls * 16);                          \
            CP16(ab + off, &Ab[(size_t)(q0 + r_) * KQK + kb]);                 \
            CP16(bb + off, &Bb[(size_t)(c0 + r_) * KQK + kb]);                 \
        }                                                                      \
        CP_COMMIT();                                                           \
    } while (0)

    float acc[4][4][4] = {};
    SC_LOAD(0, 0);
    for (int c = 0; c < 3; c++) {
        const int st = c & 1;
        if (c + 1 < 3) {
            SC_LOAD(c + 1, st ^ 1);
            asm volatile("cp.async.wait_group 1;");
        } else {
            asm volatile("cp.async.wait_group 0;");
        }
        __syncthreads();
        const uint32_t abase = sb + st * 16384;
        const uint32_t bbase = sb + 32768 + st * 16384;
#pragma unroll
        for (int ks = 0; ks < 4; ks++) {
            uint32_t af[4][4];
#pragma unroll
            for (int mt = 0; mt < 4; mt++) {
                int row = warp_m * 64 + mt * 16 + (lane & 15);
                int seg = ks * 2 + (lane >> 4);
                ldm_x4(af[mt], abase + SW128(row * 128 + seg * 16));
            }
            uint32_t bf[2][4];
#pragma unroll
            for (int h = 0; h < 2; h++) {
                int row = warp_n * 32 + h * 16 + ((lane >> 4) & 1) * 8 + (lane & 7);
                int seg = ks * 2 + ((lane >> 3) & 1);
                ldm_x4(bf[h], bbase + SW128(row * 128 + seg * 16));
            }
#pragma unroll
            for (int mt = 0; mt < 4; mt++)
#pragma unroll
                for (int nt = 0; nt < 4; nt++)
                    mma_bf16(acc[mt][nt], af[mt],
                             bf[nt >> 1][(nt & 1) * 2], bf[nt >> 1][(nt & 1) * 2 + 1]);
        }
        __syncthreads();
    }
#undef SC_LOAD

    float* Arow = attn + (size_t)bh * S_LEN * S_LEN;
    const int mrow = lane >> 2;
    const int ncol = 2 * (lane & 3);
#pragma unroll
    for (int mt = 0; mt < 4; mt++)
#pragma unroll
        for (int nt = 0; nt < 4; nt++) {
            int cg = c0 + warp_n * 32 + nt * 8 + ncol;
#pragma unroll
            for (int half = 0; half < 2; half++) {
                int q = q0 + warp_m * 64 + mt * 16 + mrow + half * 8;
                float2 v = {acc[mt][nt][half * 2] * 0.125f,
                            acc[mt][nt][half * 2 + 1] * 0.125f};
                *(float2*)&Arow[(size_t)q * S_LEN + cg] = v;
            }
        }
}

// ---------------------------------------------------------------------------
// av_fused: per (bh, 128-row q-tile):
//   phase 1: online softmax stats per row (read scores once); zero-fill upper.
//   phase 2: per 64-col chunk: p = exp(s-m)*inv -> write fp32 probs to attn,
//            convert to bf16 hi/lo in smem, HMMA against V^T hi/lo chunks.
// smem: P stages 2x32K (Ph+Pl), V stages 2x16K (Vh+Vl) = 96K.
// ---------------------------------------------------------------------------
#define AV_SMEM 98304

__global__ __launch_bounds__(256) void av_fused(
    float* __restrict__ attn,
    const __nv_bfloat16* __restrict__ Vth, const __nv_bfloat16* __restrict__ Vtl,
    __nv_bfloat16* __restrict__ Acat)
{
    const int qt = blockIdx.x, bh = blockIdx.y;
    extern __shared__ __align__(1024) char smem[];
    __shared__ float s_m[128], s_inv[128];
    const int tid = threadIdx.x;
    const int wid = tid >> 5, lane = tid & 31;
    const int warp_m = wid & 3;           // 32 q rows
    const int warp_n = wid >> 2;          // 32 hd cols
    const uint32_t sb = smem_u32(smem);
    const int q0 = qt * 128;
    const int kend = q0 + 128;
    const int nch = kend >> 6;

    float* attnb = attn + (size_t)bh * S_LEN * S_LEN;
    const __nv_bfloat16* Vhb = Vth + (size_t)bh * HD * S_LEN;
    const __nv_bfloat16* Vlb = Vtl + (size_t)bh * HD * S_LEN;

    const int ls = tid & 7;
    const int lr = tid >> 3;
    const int prow = tid >> 1;
    const int pcol = (tid & 1) * 32;

#define AVF_LOADV(chunk, stage) do {                                           \
        uint32_t vb_ = sb + 65536 + (stage) * 16384;                           \
        size_t kb_ = (size_t)(chunk) * 64 + ls * 8;                            \
        _Pragma("unroll")                                                      \
        for (int i_ = 0; i_ < 2; i_++) {                                       \
            int r_ = lr + 32 * i_;                                             \
            uint32_t off_ = SW128(r_ * 128 + ls * 16);                         \
            CP16(vb_ + off_,        &Vhb[(size_t)r_ * S_LEN + kb_]);           \
            CP16(vb_ + 8192 + off_, &Vlb[(size_t)r_ * S_LEN + kb_]);           \
        }                                                                      \
        CP_COMMIT();                                                           \
    } while (0)

#define COMPUTE_P(chunk, stage) do {                                           \
        const int k0_ = (chunk) * 64;                                          \
        const int q_ = q0 + prow;                                              \
        const float m_ = s_m[prow], inv_ = s_inv[prow];                        \
        float* srow_ = attnb + (size_t)q_ * S_LEN + k0_;                       \
        char* ph_ = smem + (stage) * 32768;                                    \
        _Pragma("unroll")                                                      \
        for (int j8_ = 0; j8_ < 8; j8_++) {                                    \
            int c_ = pcol + j8_ * 4;                                           \
            float4 v_ = *(const float4*)&srow_[c_];                            \
            int kg_ = k0_ + c_;                                                \
            float p0_ = (kg_ + 0 <= q_) ? __expf(v_.x - m_) * inv_ : 0.f;      \
            float p1_ = (kg_ + 1 <= q_) ? __expf(v_.y - m_) * inv_ : 0.f;      \
            float p2_ = (kg_ + 2 <= q_) ? __expf(v_.z - m_) * inv_ : 0.f;      \
            float p3_ = (kg_ + 3 <= q_) ? __expf(v_.w - m_) * inv_ : 0.f;      \
            float4 pv_ = {p0_, p1_, p2_, p3_};                                 \
            *(float4*)&srow_[c_] = pv_;                                        \
            __nv_bfloat16 h0_ = __float2bfloat16(p0_);                         \
            __nv_bfloat16 h1_ = __float2bfloat16(p1_);                         \
            __nv_bfloat16 h2_ = __float2bfloat16(p2_);                         \
            __nv_bfloat16 h3_ = __float2bfloat16(p3_);                         \
            __nv_bfloat16 l0_ = __float2bfloat16(p0_ - __bfloat162float(h0_)); \
            __nv_bfloat16 l1_ = __float2bfloat16(p1_ - __bfloat162float(h1_)); \
            __nv_bfloat16 l2_ = __float2bfloat16(p2_ - __bfloat162float(h2_)); \
            __nv_bfloat16 l3_ = __float2bfloat16(p3_ - __bfloat162float(h3_)); \
            __nv_bfloat162 H01_ = __halves2bfloat162(h0_, h1_);                \
            __nv_bfloat162 H23_ = __halves2bfloat162(h2_, h3_);                \
            __nv_bfloat162 L01_ = __halves2bfloat162(l0_, l1_);                \
            __nv_bfloat162 L23_ = __halves2bfloat162(l2_, l3_);                \
            uint32_t off_ = SW128(prow * 128 + c_ * 2);                        \
            uint2 Hp_, Lp_;                                                    \
            Hp_.x = *(uint32_t*)&H01_; Hp_.y = *(uint32_t*)&H23_;              \
            Lp_.x = *(uint32_t*)&L01_; Lp_.y = *(uint32_t*)&L23_;              \
            *(uint2*)(ph_ + off_) = Hp_;                                       \
            *(uint2*)(ph_ + 16384 + off_) = Lp_;                               \
        }                                                                      \
    } while (0)

    // start V chunk 0 load immediately
    AVF_LOADV(0, 0);

    // ---------------- phase 1: per-row softmax stats ------------------------
    {
        const int rb = wid * 16;
        for (int r8 = 0; r8 < 16; r8++) {
            const int row = rb + r8;
            const int q = q0 + row;
            const float* srow = attnb + (size_t)q * S_LEN;
            float m = -3.0e38f, s = 0.f;
            for (int c = lane * 4; c < kend; c += 128) {
                float4 v = *(const float4*)&srow[c];
                float x0 = (c + 0 <= q) ? v.x : -3.0e38f;
                float x1 = (c + 1 <= q) ? v.y : -3.0e38f;
                float x2 = (c + 2 <= q) ? v.z : -3.0e38f;
                float x3 = (c + 3 <= q) ? v.w : -3.0e38f;
                float nm = fmaxf(fmaxf(fmaxf(x0, x1), fmaxf(x2, x3)), m);
                s = s * __expf(m - nm) + __expf(x0 - nm) + __expf(x1 - nm)
                  + __expf(x2 - nm) + __expf(x3 - nm);
                m = nm;
            }
#pragma unroll
            for (int o = 16; o; o >>= 1) {
                float om = __shfl_xor_sync(~0u, m, o);
                float os = __shfl_xor_sync(~0u, s, o);
                float nm = fmaxf(m, om);
                s = s * __expf(m - nm) + os * __expf(om - nm);
                m = nm;
            }
            if (lane == 0) { s_m[row] = m; s_inv[row] = 1.f / s; }
        }
    }
    __syncthreads();

    // zero-fill masked upper region of attn output for this q-tile
    {
        const int rb = wid * 16;
        const float4 z = {0.f, 0.f, 0.f, 0.f};
        for (int r8 = 0; r8 < 16; r8++) {
            float* srow = attnb + (size_t)(q0 + rb + r8) * S_LEN;
            for (int c = kend + lane * 4; c < S_LEN; c += 128)
                *(float4*)&srow[c] = z;
        }
    }

    // first P chunk
    COMPUTE_P(0, 0);

    // ---------------- phase 2: chunked P conversion + HMMA ------------------
    float acc[2][4][4] = {};
    for (int c = 0; c < nch; c++) {
        const int st = c & 1;
        if (c + 1 < nch) {
            AVF_LOADV(c + 1, st ^ 1);
            asm volatile("cp.async.wait_group 1;");
        } else {
            asm volatile("cp.async.wait_group 0;");
        }
        __syncthreads();
        if (c + 1 < nch) COMPUTE_P(c + 1, st ^ 1);

        const uint32_t pbase = sb + st * 32768;
        const uint32_t vbase = sb + 65536 + st * 16384;
#pragma unroll
        for (int ks = 0; ks < 4; ks++) {
            uint32_t ah[2][4], al[2][4];
#pragma unroll
            for (int mt = 0; mt < 2; mt++) {
                int row = warp_m * 32 + mt * 16 + (lane & 15);
                int seg = ks * 2 + (lane >> 4);
                uint32_t off = SW128(row * 128 + seg * 16);
                ldm_x4(ah[mt], pbase + off);
                ldm_x4(al[mt], pbase + 16384 + off);
            }
            uint32_t bh_[2][4], bl_[2][4];
#pragma unroll
            for (int h = 0; h < 2; h++) {
                int row = warp_n * 32 + h * 16 + ((lane >> 4) & 1) * 8 + (lane & 7);
                int seg = ks * 2 + ((lane >> 3) & 1);
                uint32_t off = SW128(row * 128 + seg * 16);
                ldm_x4(bh_[h], vbase + off);
                ldm_x4(bl_[h], vbase + 8192 + off);
            }
#pragma unroll
            for (int mt = 0; mt < 2; mt++)
#pragma unroll
                for (int nt = 0; nt < 4; nt++) {
                    uint32_t vh0 = bh_[nt >> 1][(nt & 1) * 2];
                    uint32_t vh1 = bh_[nt >> 1][(nt & 1) * 2 + 1];
                    uint32_t vl0 = bl_[nt >> 1][(nt & 1) * 2];
                    uint32_t vl1 = bl_[nt >> 1][(nt & 1) * 2 + 1];
                    mma_bf16(acc[mt][nt], ah[mt], vh0, vh1);
                    mma_bf16(acc[mt][nt], al[mt], vh0, vh1);
                    mma_bf16(acc[mt][nt], ah[mt], vl0, vl1);
                }
        }
        __syncthreads();
    }
#undef AVF_LOADV
#undef COMPUTE_P

    // epilogue: write A in split-cat layout [hi,hi,lo] for the Wo GEMM
    const int bb = bh / NH, h = bh % NH;
    const int mrow = lane >> 2;
    const int ncol = 2 * (lane & 3);
#pragma unroll
    for (int mt = 0; mt < 2; mt++)
#pragma unroll
        for (int nt = 0; nt < 4; nt++) {
            int hd = warp_n * 32 + nt * 8 + ncol;
            int cc = h * HD + hd;
#pragma unroll
            for (int half = 0; half < 2; half++) {
                int s = q0 + warp_m * 32 + mt * 16 + mrow + half * 8;
                float v0 = acc[mt][nt][half * 2];
                float v1 = acc[mt][nt][half * 2 + 1];
                __nv_bfloat16 h0 = __float2bfloat16(v0);
                __nv_bfloat16 h1 = __float2bfloat16(v1);
                __nv_bfloat16 l0 = __float2bfloat16(v0 - __bfloat162float(h0));
                __nv_bfloat16 l1 = __float2bfloat16(v1 - __bfloat162float(h1));
                size_t base = ((size_t)(bb * S_LEN + s)) * KCAT + cc;
                *(__nv_bfloat162*)&Acat[base]          = __halves2bfloat162(h0, h1);
                *(__nv_bfloat162*)&Acat[base + DM]     = __halves2bfloat162(h0, h1);
                *(__nv_bfloat162*)&Acat[base + 2 * DM] = __halves2bfloat162(l0, l1);
            }
        }
}

// ---------------------------------------------------------------------------
extern "C" void kernel_launch(void* const* d_in, const int* in_sizes, int n_in,
                              void* d_out, int out_size)
{
    const float* X  = (const float*)d_in[0];
    const float* Wq = (const float*)d_in[1];
    const float* bq = (const float*)d_in[2];
    const float* Wk = (const float*)d_in[3];
    const float* bk = (const float*)d_in[4];
    const float* Wv = (const float*)d_in[5];
    const float* bv = (const float*)d_in[6];
    const float* Wo = (const float*)d_in[7];
    const float* bo = (const float*)d_in[8];

    float* out  = (float*)d_out;
    float* attn = out + (size_t)MROWS * DM;

    __nv_bfloat16 *gXc, *gAc, *gWq, *gWk, *gWv, *gWo;
    __nv_bfloat16 *gQc, *gKc, *gVh, *gVl;
    cudaGetSymbolAddress((void**)&gXc, g_Xcat);
    cudaGetSymbolAddress((void**)&gAc, g_Acat);
    cudaGetSymbolAddress((void**)&gWq, g_Wqc);
    cudaGetSymbolAddress((void**)&gWk, g_Wkc);
    cudaGetSymbolAddress((void**)&gWv, g_Wvc);
    cudaGetSymbolAddress((void**)&gWo, g_Woc);
    cudaGetSymbolAddress((void**)&gQc, g_Qc);
    cudaGetSymbolAddress((void**)&gKc, g_Kc);
    cudaGetSymbolAddress((void**)&gVh, g_Vth);
    cudaGetSymbolAddress((void**)&gVl, g_Vtl);

    static int smem_set = 0;
    if (!smem_set) {
        cudaFuncSetAttribute(gemm_mma, cudaFuncAttributeMaxDynamicSharedMemorySize, GEMM_SMEM);
        cudaFuncSetAttribute(scores_mma, cudaFuncAttributeMaxDynamicSharedMemorySize, SC_SMEM);
        cudaFuncSetAttribute(av_fused, cudaFuncAttributeMaxDynamicSharedMemorySize, AV_SMEM);
        smem_set = 1;
    }

    dim3 blk(256);
    convert_cat<<<512, blk>>>(Wq, gWq, DM, 1);
    convert_cat<<<512, blk>>>(Wk, gWk, DM, 1);
    convert_cat<<<512, blk>>>(Wv, gWv, DM, 1);
    convert_cat<<<512, blk>>>(Wo, gWo, DM, 1);
    convert_cat<<<1024, blk>>>(X, gXc, MROWS, 0);

    dim3 ggemm(DM / 128, MROWS / 128);
    gemm_mma<<<ggemm, blk, GEMM_SMEM>>>(gXc, gWq, bq, nullptr, gQc, nullptr, 1);
    gemm_mma<<<ggemm, blk, GEMM_SMEM>>>(gXc, gWk, bk, nullptr, gKc, nullptr, 2);
    gemm_mma<<<ggemm, blk, GEMM_SMEM>>>(gXc, gWv, bv, nullptr, gVh, gVl, 3);

    dim3 gsc(S_LEN / 128, S_LEN / 128, BHN);
    scores_mma<<<gsc, blk, SC_SMEM>>>(gQc, gKc, attn);

    dim3 gav(S_LEN / 128, BHN);
    av_fused<<<gav, blk, AV_SMEM>>>(attn, gVh, gVl, gAc);

    gemm_mma<<<ggemm, blk, GEMM_SMEM>>>(gAc, gWo, bo, out, nullptr, nullptr, 0);
}

// round 7
// speedup vs baseline: 1.5369x; 1.5369x over previous
#include <cuda_runtime.h>
#include <cuda_bf16.h>
#include <math.h>
#include <stdint.h>

#define S_LEN 2048
#define DM    1024
#define NH    16
#define HD    64
#define BATCH 2
#define BHN   (BATCH * NH)        // 32
#define MROWS (BATCH * S_LEN)     // 4096
#define KCAT  3072                // 3 x DM (hi,hi,lo | hi,lo,hi)
#define NKCH  (KCAT / 64)         // 48
#define KQK   192                 // 3 x HD

// ---------------- scratch (__device__ globals) ------------------------------
__device__ __nv_bfloat16 g_Xcat[(size_t)MROWS * KCAT];
__device__ __nv_bfloat16 g_Acat[(size_t)MROWS * KCAT];
__device__ __nv_bfloat16 g_Wqc[(size_t)DM * KCAT];
__device__ __nv_bfloat16 g_Wkc[(size_t)DM * KCAT];
__device__ __nv_bfloat16 g_Wvc[(size_t)DM * KCAT];
__device__ __nv_bfloat16 g_Woc[(size_t)DM * KCAT];
__device__ __nv_bfloat16 g_Qc[(size_t)BHN * S_LEN * KQK];   // [hi,hi,lo]
__device__ __nv_bfloat16 g_Kc[(size_t)BHN * S_LEN * KQK];   // [hi,lo,hi]
__device__ __nv_bfloat16 g_Vth[(size_t)BHN * HD * S_LEN];   // V^T hi
__device__ __nv_bfloat16 g_Vtl[(size_t)BHN * HD * S_LEN];   // V^T lo
__device__ __nv_bfloat16 g_Ph[(size_t)BHN * S_LEN * S_LEN]; // P hi
__device__ __nv_bfloat16 g_Pl[(size_t)BHN * S_LEN * S_LEN]; // P lo

// ---------------- helpers ---------------------------------------------------
__device__ __forceinline__ uint32_t smem_u32(const void* p) {
    uint32_t a;
    asm("{ .reg .u64 t; cvta.to.shared.u64 t, %1; cvt.u32.u64 %0, t; }"
        : "=r"(a) : "l"(p));
    return a;
}
#define SW128(o) ((o) ^ (((o) >> 3) & 0x70))

__device__ __forceinline__ void ldm_x4(uint32_t* r, uint32_t addr) {
    asm volatile("ldmatrix.sync.aligned.m8n8.x4.shared.b16 {%0,%1,%2,%3}, [%4];"
                 : "=r"(r[0]), "=r"(r[1]), "=r"(r[2]), "=r"(r[3]) : "r"(addr));
}
__device__ __forceinline__ void mma_bf16(float* c, const uint32_t* a,
                                         uint32_t b0, uint32_t b1) {
    asm volatile(
        "mma.sync.aligned.m16n8k16.row.col.f32.bf16.bf16.f32 "
        "{%0,%1,%2,%3}, {%4,%5,%6,%7}, {%8,%9}, {%0,%1,%2,%3};"
        : "+f"(c[0]), "+f"(c[1]), "+f"(c[2]), "+f"(c[3])
        : "r"(a[0]), "r"(a[1]), "r"(a[2]), "r"(a[3]), "r"(b0), "r"(b1));
}
#define CP16(dst, src) \
    asm volatile("cp.async.cg.shared.global [%0], [%1], 16;" :: "r"(dst), "l"(src))
#define CP_COMMIT() asm volatile("cp.async.commit_group;")

// ---------------------------------------------------------------------------
// fp32 -> bf16 split-concat.  mode 0 (A): [hi,hi,lo]   mode 1 (B): [hi,lo,hi]
// ---------------------------------------------------------------------------
__global__ __launch_bounds__(256) void convert_cat(
    const float* __restrict__ src, __nv_bfloat16* __restrict__ dst,
    int rows, int mode)
{
    int n = rows * (DM / 4);
    for (int i = blockIdx.x * blockDim.x + threadIdx.x; i < n;
         i += gridDim.x * blockDim.x) {
        int r = i / (DM / 4), cq = i - r * (DM / 4);
        float4 v = *(const float4*)&src[(size_t)r * DM + cq * 4];
        float f[4] = {v.x, v.y, v.z, v.w};
        __nv_bfloat16 hi[4], lo[4];
#pragma unroll
        for (int j = 0; j < 4; j++) {
            hi[j] = __float2bfloat16(f[j]);
            lo[j] = __float2bfloat16(f[j] - __bfloat162float(hi[j]));
        }
        __nv_bfloat162 h01 = __halves2bfloat162(hi[0], hi[1]);
        __nv_bfloat162 h23 = __halves2bfloat162(hi[2], hi[3]);
        __nv_bfloat162 l01 = __halves2bfloat162(lo[0], lo[1]);
        __nv_bfloat162 l23 = __halves2bfloat162(lo[2], lo[3]);
        size_t base = (size_t)r * KCAT + cq * 4;
        __nv_bfloat162* d0 = (__nv_bfloat162*)&dst[base];
        __nv_bfloat162* d1 = (__nv_bfloat162*)&dst[base + DM];
        __nv_bfloat162* d2 = (__nv_bfloat162*)&dst[base + 2 * DM];
        d0[0] = h01; d0[1] = h23;
        if (mode == 0) { d1[0] = h01; d1[1] = h23; d2[0] = l01; d2[1] = l23; }
        else           { d1[0] = l01; d1[1] = l23; d2[0] = h01; d2[1] = h23; }
    }
}

// ---------------------------------------------------------------------------
// mma.sync bf16 GEMM: C[r,c] = sum_k A[r,k]*B[c,k] + bias[c]
// 4-stage cp.async pipeline (lookahead 2), single barrier per k-chunk.
// omode 0: fp32 row-major.  1: Q split A-layout.  2: K split B-layout.
// omode 3: V transposed hi/lo planes.
// ---------------------------------------------------------------------------
#define GEMM_SMEM 131072   // A: 4x16K, B: 4x16K

__global__ __launch_bounds__(256) void gemm_mma(
    const __nv_bfloat16* __restrict__ A, const __nv_bfloat16* __restrict__ B,
    const float* __restrict__ bias, float* __restrict__ outf,
    __nv_bfloat16* __restrict__ ob1, __nv_bfloat16* __restrict__ ob2, int omode)
{
    extern __shared__ __align__(1024) char smem[];
    const int tid = threadIdx.x;
    const int wid = tid >> 5, lane = tid & 31;
    const int warp_m = wid >> 2;
    const int warp_n = wid & 3;
    const uint32_t sb = smem_u32(smem);

    const int r0 = blockIdx.y * 128, c0 = blockIdx.x * 128;
    const int ls = tid & 7;
    const int lr = tid >> 3;

#define LOAD_STAGE(chunk, stage) do {                                          \
        uint32_t ab = sb + (stage) * 16384;                                    \
        uint32_t bb = sb + 65536 + (stage) * 16384;                            \
        size_t kb = (size_t)(chunk) * 64 + ls * 8;                             \
        _Pragma("unroll")                                                      \
        for (int i_ = 0; i_ < 4; i_++) {                                       \
            int r_ = lr + 32 * i_;                                             \
            uint32_t off = SW128(r_ * 128 + ls * 16);                          \
            CP16(ab + off, &A[(size_t)(r0 + r_) * KCAT + kb]);                 \
            CP16(bb + off, &B[(size_t)(c0 + r_) * KCAT + kb]);                 \
        }                                                                      \
        CP_COMMIT();                                                           \
    } while (0)

    float acc[4][4][4] = {};
    LOAD_STAGE(0, 0);
    LOAD_STAGE(1, 1);

    for (int c = 0; c < NKCH; c++) {
        if (c + 2 < NKCH) LOAD_STAGE(c + 2, (c + 2) & 3);
        else              CP_COMMIT();
        asm volatile("cp.async.wait_group 2;");
        __syncthreads();

        const uint32_t abase = sb + (c & 3) * 16384;
        const uint32_t bbase = sb + 65536 + (c & 3) * 16384;
#pragma unroll
        for (int ks = 0; ks < 4; ks++) {
            uint32_t af[4][4];
#pragma unroll
            for (int mt = 0; mt < 4; mt++) {
                int row = warp_m * 64 + mt * 16 + (lane & 15);
                int seg = ks * 2 + (lane >> 4);
                ldm_x4(af[mt], abase + SW128(row * 128 + seg * 16));
            }
            uint32_t bf[2][4];
#pragma unroll
            for (int h = 0; h < 2; h++) {
                int row = warp_n * 32 + h * 16 + ((lane >> 4) & 1) * 8 + (lane & 7);
                int seg = ks * 2 + ((lane >> 3) & 1);
                ldm_x4(bf[h], bbase + SW128(row * 128 + seg * 16));
            }
#pragma unroll
            for (int mt = 0; mt < 4; mt++)
#pragma unroll
                for (int nt = 0; nt < 4; nt++)
                    mma_bf16(acc[mt][nt], af[mt],
                             bf[nt >> 1][(nt & 1) * 2], bf[nt >> 1][(nt & 1) * 2 + 1]);
        }
    }
#undef LOAD_STAGE

    const int mrow = lane >> 2;
    const int ncol = 2 * (lane & 3);
#pragma unroll
    for (int mt = 0; mt < 4; mt++) {
#pragma unroll
        for (int nt = 0; nt < 4; nt++) {
            int cg = c0 + warp_n * 32 + nt * 8 + ncol;
            float b0 = __ldg(&bias[cg]), b1 = __ldg(&bias[cg + 1]);
#pragma unroll
            for (int half = 0; half < 2; half++) {
                int r = r0 + warp_m * 64 + mt * 16 + mrow + half * 8;
                float v0 = acc[mt][nt][half * 2] + b0;
                float v1 = acc[mt][nt][half * 2 + 1] + b1;
                if (omode == 0) {
                    float2 v = {v0, v1};
                    *(float2*)&outf[(size_t)r * DM + cg] = v;
                } else {
                    int bb = r >> 11, s = r & (S_LEN - 1);
                    int h = cg >> 6, hd = cg & 63;
                    __nv_bfloat16 h0 = __float2bfloat16(v0);
                    __nv_bfloat16 h1 = __float2bfloat16(v1);
                    __nv_bfloat16 l0 = __float2bfloat16(v0 - __bfloat162float(h0));
                    __nv_bfloat16 l1 = __float2bfloat16(v1 - __bfloat162float(h1));
                    __nv_bfloat162 hh = __halves2bfloat162(h0, h1);
                    __nv_bfloat162 ll = __halves2bfloat162(l0, l1);
                    if (omode == 3) {
                        size_t pb = ((size_t)(bb * NH + h) * HD + hd) * S_LEN + s;
                        ob1[pb] = h0; ob1[pb + S_LEN] = h1;
                        ob2[pb] = l0; ob2[pb + S_LEN] = l1;
                    } else {
                        size_t base = ((size_t)(bb * NH + h) * S_LEN + s) * KQK + hd;
                        *(__nv_bfloat162*)&ob1[base] = hh;
                        if (omode == 1) {
                            *(__nv_bfloat162*)&ob1[base + HD] = hh;
                            *(__nv_bfloat162*)&ob1[base + 2 * HD] = ll;
                        } else {
                            *(__nv_bfloat162*)&ob1[base + HD] = ll;
                            *(__nv_bfloat162*)&ob1[base + 2 * HD] = hh;
                        }
                    }
                }
            }
        }
    }
}

// ---------------------------------------------------------------------------
// scores_mma: attn[bh,q,k] = 0.125 * sum Q*K  via bf16 split (K'=192)
// ---------------------------------------------------------------------------
#define SC_SMEM 65536

__global__ __launch_bounds__(256) void scores_mma(
    const __nv_bfloat16* __restrict__ Qc, const __nv_bfloat16* __restrict__ Kc,
    float* __restrict__ attn)
{
    const int kt = blockIdx.x, qt = blockIdx.y, bh = blockIdx.z;
    if (kt > qt) return;
    extern __shared__ __align__(1024) char smem[];
    const int tid = threadIdx.x;
    const int wid = tid >> 5, lane = tid & 31;
    const int warp_m = wid >> 2;
    const int warp_n = wid & 3;
    const uint32_t sb = smem_u32(smem);
    const int q0 = qt * 128, c0 = kt * 128;

    const __nv_bfloat16* Ab = Qc + (size_t)bh * S_LEN * KQK;
    const __nv_bfloat16* Bb = Kc + (size_t)bh * S_LEN * KQK;
    const int ls = tid & 7;
    const int lr = tid >> 3;

#define SC_LOAD(chunk, stage) do {                                             \
        uint32_t ab = sb + (stage) * 16384;                                    \
        uint32_t bb = sb + 32768 + (stage) * 16384;                            \
        size_t kb = (size_t)(chunk) * 64 + ls * 8;                             \
        _Pragma("unroll")                                                      \
        for (int i_ = 0; i_ < 4; i_++) {                                       \
            int r_ = lr + 32 * i_;                                             \
            uint32_t off = SW128(r_ * 128 + ls * 16);                          \
            CP16(ab + off, &Ab[(size_t)(q0 + r_) * KQK + kb]);                 \
            CP16(bb + off, &Bb[(size_t)(c0 + r_) * KQK + kb]);                 \
        }                                                                      \
        CP_COMMIT();                                                           \
    } while (0)

    float acc[4][4][4] = {};
    SC_LOAD(0, 0);
    for (int c = 0; c < 3; c++) {
        const int st = c & 1;
        if (c + 1 < 3) {
            SC_LOAD(c + 1, st ^ 1);
            asm volatile("cp.async.wait_group 1;");
        } else {
            asm volatile("cp.async.wait_group 0;");
        }
        __syncthreads();
        const uint32_t abase = sb + st * 16384;
        const uint32_t bbase = sb + 32768 + st * 16384;
#pragma unroll
        for (int ks = 0; ks < 4; ks++) {
            uint32_t af[4][4];
#pragma unroll
            for (int mt = 0; mt < 4; mt++) {
                int row = warp_m * 64 + mt * 16 + (lane & 15);
                int seg = ks * 2 + (lane >> 4);
                ldm_x4(af[mt], abase + SW128(row * 128 + seg * 16));
            }
            uint32_t bf[2][4];
#pragma unroll
            for (int h = 0; h < 2; h++) {
                int row = warp_n * 32 + h * 16 + ((lane >> 4) & 1) * 8 + (lane & 7);
                int seg = ks * 2 + ((lane >> 3) & 1);
                ldm_x4(bf[h], bbase + SW128(row * 128 + seg * 16));
            }
#pragma unroll
            for (int mt = 0; mt < 4; mt++)
#pragma unroll
                for (int nt = 0; nt < 4; nt++)
                    mma_bf16(acc[mt][nt], af[mt],
                             bf[nt >> 1][(nt & 1) * 2], bf[nt >> 1][(nt & 1) * 2 + 1]);
        }
        __syncthreads();
    }
#undef SC_LOAD

    float* Arow = attn + (size_t)bh * S_LEN * S_LEN;
    const int mrow = lane >> 2;
    const int ncol = 2 * (lane & 3);
#pragma unroll
    for (int mt = 0; mt < 4; mt++)
#pragma unroll
        for (int nt = 0; nt < 4; nt++) {
            int cg = c0 + warp_n * 32 + nt * 8 + ncol;
#pragma unroll
            for (int half = 0; half < 2; half++) {
                int q = q0 + warp_m * 64 + mt * 16 + mrow + half * 8;
                float2 v = {acc[mt][nt][half * 2] * 0.125f,
                            acc[mt][nt][half * 2 + 1] * 0.125f};
                *(float2*)&Arow[(size_t)q * S_LEN + cg] = v;
            }
        }
}

// ---------------------------------------------------------------------------
// Row-wise causal softmax; writes fp32 probs (full row, covers poison) + bf16
// hi/lo planes ONLY up to the 128-row tile's k boundary (all av_mma reads).
// ---------------------------------------------------------------------------
__global__ __launch_bounds__(256) void softmax_kernel(
    float* __restrict__ attn, __nv_bfloat16* __restrict__ Ph,
    __nv_bfloat16* __restrict__ Pl)
{
    const int q = blockIdx.x, bh = blockIdx.y;
    const size_t rbase = ((size_t)bh * S_LEN + q) * S_LEN;
    float* row = attn + rbase;
    const int tid = threadIdx.x;
    const int valid = q + 1;
    const int tile_kend = (q & ~127) + 128;     // av tile boundary
    const int b0 = 4 * tid, b1 = 4 * (tid + 256);

    float4 v0 = {-INFINITY, -INFINITY, -INFINITY, -INFINITY}, v1 = v0;
    if (b0 < valid) v0 = *(const float4*)&row[b0];
    if (b1 < valid) v1 = *(const float4*)&row[b1];
    float vals[8] = {v0.x, v0.y, v0.z, v0.w, v1.x, v1.y, v1.z, v1.w};

    float mx = -INFINITY;
#pragma unroll
    for (int i = 0; i < 8; i++) {
        int k = (i < 4) ? (b0 + i) : (b1 + i - 4);
        if (k >= valid) vals[i] = -INFINITY;
        mx = fmaxf(mx, vals[i]);
    }
#pragma unroll
    for (int o = 16; o; o >>= 1) mx = fmaxf(mx, __shfl_xor_sync(~0u, mx, o));
    __shared__ float sred[8];
    if ((tid & 31) == 0) sred[tid >> 5] = mx;
    __syncthreads();
    mx = sred[0];
#pragma unroll
    for (int i = 1; i < 8; i++) mx = fmaxf(mx, sred[i]);
    __syncthreads();

    float sum = 0.f;
#pragma unroll
    for (int i = 0; i < 8; i++) {
        float e = __expf(vals[i] - mx);
        vals[i] = e;
        sum += e;
    }
#pragma unroll
    for (int o = 16; o; o >>= 1) sum += __shfl_xor_sync(~0u, sum, o);
    if ((tid & 31) == 0) sred[tid >> 5] = sum;
    __syncthreads();
    sum = 0.f;
#pragma unroll
    for (int i = 0; i < 8; i++) sum += sred[i];
    const float inv = 1.f / sum;

    float p[8];
    __nv_bfloat16 hh[8], ll[8];
#pragma unroll
    for (int i = 0; i < 8; i++) {
        p[i] = vals[i] * inv;
        hh[i] = __float2bfloat16(p[i]);
        ll[i] = __float2bfloat16(p[i] - __bfloat162float(hh[i]));
    }
    float4 w0 = {p[0], p[1], p[2], p[3]};
    float4 w1 = {p[4], p[5], p[6], p[7]};
    *(float4*)&row[b0] = w0;
    *(float4*)&row[b1] = w1;
    if (b0 < tile_kend) {
#pragma unroll
        for (int j = 0; j < 2; j++) {
            *(__nv_bfloat162*)&Ph[rbase + b0 + 2*j] = __halves2bfloat162(hh[2*j], hh[2*j+1]);
            *(__nv_bfloat162*)&Pl[rbase + b0 + 2*j] = __halves2bfloat162(ll[2*j], ll[2*j+1]);
        }
    }
    if (b1 < tile_kend) {
#pragma unroll
        for (int j = 0; j < 2; j++) {
            *(__nv_bfloat162*)&Ph[rbase + b1 + 2*j] = __halves2bfloat162(hh[4+2*j], hh[5+2*j]);
            *(__nv_bfloat162*)&Pl[rbase + b1 + 2*j] = __halves2bfloat162(ll[4+2*j], ll[5+2*j]);
        }
    }
}

// ---------------------------------------------------------------------------
// av_mma: A[q,hd] = sum_k P[q,k]*V[k,hd] via Ph*Vh + Pl*Vh + Ph*Vl.
// 128(q) x 64(hd) tile; causal chunk bound. Writes A in split-cat layout.
// ---------------------------------------------------------------------------
#define AV_SMEM 98304

__global__ __launch_bounds__(256) void av_mma(
    const __nv_bfloat16* __restrict__ Ph, const __nv_bfloat16* __restrict__ Pl,
    const __nv_bfloat16* __restrict__ Vth, const __nv_bfloat16* __restrict__ Vtl,
    __nv_bfloat16* __restrict__ Acat)
{
    const int qt = blockIdx.x, bh = blockIdx.y;
    extern __shared__ __align__(1024) char smem[];
    const int tid = threadIdx.x;
    const int wid = tid >> 5, lane = tid & 31;
    const int warp_m = wid & 3;           // 32 q rows each
    const int warp_n = wid >> 2;          // 32 hd cols each
    const uint32_t sb = smem_u32(smem);
    const int q0 = qt * 128;

    const __nv_bfloat16* Phb = Ph + (size_t)bh * S_LEN * S_LEN;
    const __nv_bfloat16* Plb = Pl + (size_t)bh * S_LEN * S_LEN;
    const __nv_bfloat16* Vhb = Vth + (size_t)bh * HD * S_LEN;
    const __nv_bfloat16* Vlb = Vtl + (size_t)bh * HD * S_LEN;

    const int ls = tid & 7;
    const int lr = tid >> 3;
    const int nch = (q0 + 128) / 64;

#define AV_LOAD(chunk, stage) do {                                             \
        uint32_t base = sb + (stage) * 49152;                                  \
        size_t kb = (size_t)(chunk) * 64 + ls * 8;                             \
        _Pragma("unroll")                                                      \
        for (int i_ = 0; i_ < 4; i_++) {                                       \
            int r_ = lr + 32 * i_;                                             \
            uint32_t off = SW128(r_ * 128 + ls * 16);                          \
            CP16(base + off,         &Phb[(size_t)(q0 + r_) * S_LEN + kb]);    \
            CP16(base + 16384 + off, &Plb[(size_t)(q0 + r_) * S_LEN + kb]);    \
        }                                                                      \
        _Pragma("unroll")                                                      \
        for (int i_ = 0; i_ < 2; i_++) {                                       \
            int r_ = lr + 32 * i_;                                             \
            uint32_t off = SW128(r_ * 128 + ls * 16);                          \
            CP16(base + 32768 + off, &Vhb[(size_t)r_ * S_LEN + kb]);           \
            CP16(base + 40960 + off, &Vlb[(size_t)r_ * S_LEN + kb]);           \
        }                                                                      \
        CP_COMMIT();                                                           \
    } while (0)

    float acc[2][4][4] = {};
    AV_LOAD(0, 0);
    for (int c = 0; c < nch; c++) {
        const int st = c & 1;
        if (c + 1 < nch) {
            AV_LOAD(c + 1, st ^ 1);
            asm volatile("cp.async.wait_group 1;");
        } else {
            asm volatile("cp.async.wait_group 0;");
        }
        __syncthreads();
        const uint32_t base = sb + st * 49152;
#pragma unroll
        for (int ks = 0; ks < 4; ks++) {
            uint32_t ah[2][4], al[2][4];
#pragma unroll
            for (int mt = 0; mt < 2; mt++) {
                int row = warp_m * 32 + mt * 16 + (lane & 15);
                int seg = ks * 2 + (lane >> 4);
                uint32_t off = SW128(row * 128 + seg * 16);
                ldm_x4(ah[mt], base + off);
                ldm_x4(al[mt], base + 16384 + off);
            }
            uint32_t bh_[2][4], bl_[2][4];
#pragma unroll
            for (int h = 0; h < 2; h++) {
                int row = warp_n * 32 + h * 16 + ((lane >> 4) & 1) * 8 + (lane & 7);
                int seg = ks * 2 + ((lane >> 3) & 1);
                uint32_t off = SW128(row * 128 + seg * 16);
                ldm_x4(bh_[h], base + 32768 + off);
                ldm_x4(bl_[h], base + 40960 + off);
            }
#pragma unroll
            for (int mt = 0; mt < 2; mt++)
#pragma unroll
                for (int nt = 0; nt < 4; nt++) {
                    uint32_t vh0 = bh_[nt >> 1][(nt & 1) * 2];
                    uint32_t vh1 = bh_[nt >> 1][(nt & 1) * 2 + 1];
                    uint32_t vl0 = bl_[nt >> 1][(nt & 1) * 2];
                    uint32_t vl1 = bl_[nt >> 1][(nt & 1) * 2 + 1];
                    mma_bf16(acc[mt][nt], ah[mt], vh0, vh1);
                    mma_bf16(acc[mt][nt], al[mt], vh0, vh1);
                    mma_bf16(acc[mt][nt], ah[mt], vl0, vl1);
                }
        }
        __syncthreads();
    }
#undef AV_LOAD

    // epilogue: write A in split-cat layout [hi,hi,lo] for the Wo GEMM
    const int bb = bh / NH, h = bh % NH;
    const int mrow = lane >> 2;
    const int ncol = 2 * (lane & 3);
#pragma unroll
    for (int mt = 0; mt < 2; mt++)
#pragma unroll
        for (int nt = 0; nt < 4; nt++) {
            int hd = warp_n * 32 + nt * 8 + ncol;
            int cc = h * HD + hd;
#pragma unroll
            for (int half = 0; half < 2; half++) {
                int s = q0 + warp_m * 32 + mt * 16 + mrow + half * 8;
                float v0 = acc[mt][nt][half * 2];
                float v1 = acc[mt][nt][half * 2 + 1];
                __nv_bfloat16 h0 = __float2bfloat16(v0);
                __nv_bfloat16 h1 = __float2bfloat16(v1);
                __nv_bfloat16 l0 = __float2bfloat16(v0 - __bfloat162float(h0));
                __nv_bfloat16 l1 = __float2bfloat16(v1 - __bfloat162float(h1));
                size_t base = ((size_t)(bb * S_LEN + s)) * KCAT + cc;
                *(__nv_bfloat162*)&Acat[base]          = __halves2bfloat162(h0, h1);
                *(__nv_bfloat162*)&Acat[base + DM]     = __halves2bfloat162(h0, h1);
                *(__nv_bfloat162*)&Acat[base + 2 * DM] = __halves2bfloat162(l0, l1);
            }
        }
}

// ---------------------------------------------------------------------------
extern "C" void kernel_launch(void* const* d_in, const int* in_sizes, int n_in,
                              void* d_out, int out_size)
{
    const float* X  = (const float*)d_in[0];
    const float* Wq = (const float*)d_in[1];
    const float* bq = (const float*)d_in[2];
    const float* Wk = (const float*)d_in[3];
    const float* bk = (const float*)d_in[4];
    const float* Wv = (const float*)d_in[5];
    const float* bv = (const float*)d_in[6];
    const float* Wo = (const float*)d_in[7];
    const float* bo = (const float*)d_in[8];

    float* out  = (float*)d_out;
    float* attn = out + (size_t)MROWS * DM;

    __nv_bfloat16 *gXc, *gAc, *gWq, *gWk, *gWv, *gWo;
    __nv_bfloat16 *gQc, *gKc, *gVh, *gVl, *gPh, *gPl;
    cudaGetSymbolAddress((void**)&gXc, g_Xcat);
    cudaGetSymbolAddress((void**)&gAc, g_Acat);
    cudaGetSymbolAddress((void**)&gWq, g_Wqc);
    cudaGetSymbolAddress((void**)&gWk, g_Wkc);
    cudaGetSymbolAddress((void**)&gWv, g_Wvc);
    cudaGetSymbolAddress((void**)&gWo, g_Woc);
    cudaGetSymbolAddress((void**)&gQc, g_Qc);
    cudaGetSymbolAddress((void**)&gKc, g_Kc);
    cudaGetSymbolAddress((void**)&gVh, g_Vth);
    cudaGetSymbolAddress((void**)&gVl, g_Vtl);
    cudaGetSymbolAddress((void**)&gPh, g_Ph);
    cudaGetSymbolAddress((void**)&gPl, g_Pl);

    static int smem_set = 0;
    if (!smem_set) {
        cudaFuncSetAttribute(gemm_mma, cudaFuncAttributeMaxDynamicSharedMemorySize, GEMM_SMEM);
        cudaFuncSetAttribute(scores_mma, cudaFuncAttributeMaxDynamicSharedMemorySize, SC_SMEM);
        cudaFuncSetAttribute(av_mma, cudaFuncAttributeMaxDynamicSharedMemorySize, AV_SMEM);
        smem_set = 1;
    }

    dim3 blk(256);
    convert_cat<<<512, blk>>>(Wq, gWq, DM, 1);
    convert_cat<<<512, blk>>>(Wk, gWk, DM, 1);
    convert_cat<<<512, blk>>>(Wv, gWv, DM, 1);
    convert_cat<<<512, blk>>>(Wo, gWo, DM, 1);
    convert_cat<<<1024, blk>>>(X, gXc, MROWS, 0);

    dim3 ggemm(DM / 128, MROWS / 128);
    gemm_mma<<<ggemm, blk, GEMM_SMEM>>>(gXc, gWq, bq, nullptr, gQc, nullptr, 1);
    gemm_mma<<<ggemm, blk, GEMM_SMEM>>>(gXc, gWk, bk, nullptr, gKc, nullptr, 2);
    gemm_mma<<<ggemm, blk, GEMM_SMEM>>>(gXc, gWv, bv, nullptr, gVh, gVl, 3);

    dim3 gsc(S_LEN / 128, S_LEN / 128, BHN);
    scores_mma<<<gsc, blk, SC_SMEM>>>(gQc, gKc, attn);

    dim3 gsm(S_LEN, BHN);
    softmax_kernel<<<gsm, blk>>>(attn, gPh, gPl);

    dim3 gav(S_LEN / 128, BHN);
    av_mma<<<gav, blk, AV_SMEM>>>(gPh, gPl, gVh, gVl, gAc);

    gemm_mma<<<ggemm, blk, GEMM_SMEM>>>(gAc, gWo, bo, out, nullptr, nullptr, 0);
}

// round 8
// speedup vs baseline: 1.6178x; 1.0526x over previous
#include <cuda_runtime.h>
#include <cuda_bf16.h>
#include <math.h>
#include <stdint.h>

#define S_LEN 2048
#define DM    1024
#define NH    16
#define HD    64
#define BATCH 2
#define BHN   (BATCH * NH)        // 32
#define MROWS (BATCH * S_LEN)     // 4096
#define KCAT  3072                // 3 x DM (hi,hi,lo | hi,lo,hi)
#define NKCH  (KCAT / 64)         // 48
#define KQK   192                 // 3 x HD

// ---------------- scratch (__device__ globals) ------------------------------
__device__ __nv_bfloat16 g_Xcat[(size_t)MROWS * KCAT];
__device__ __nv_bfloat16 g_Acat[(size_t)MROWS * KCAT];
__device__ __nv_bfloat16 g_Wqc[(size_t)DM * KCAT];
__device__ __nv_bfloat16 g_Wkc[(size_t)DM * KCAT];
__device__ __nv_bfloat16 g_Wvc[(size_t)DM * KCAT];
__device__ __nv_bfloat16 g_Woc[(size_t)DM * KCAT];
__device__ __nv_bfloat16 g_Qc[(size_t)BHN * S_LEN * KQK];   // [hi,hi,lo]
__device__ __nv_bfloat16 g_Kc[(size_t)BHN * S_LEN * KQK];   // [hi,lo,hi]
__device__ __nv_bfloat16 g_Vth[(size_t)BHN * HD * S_LEN];   // V^T hi
__device__ __nv_bfloat16 g_Vtl[(size_t)BHN * HD * S_LEN];   // V^T lo
__device__ __nv_bfloat16 g_Ph[(size_t)BHN * S_LEN * S_LEN]; // P hi
__device__ __nv_bfloat16 g_Pl[(size_t)BHN * S_LEN * S_LEN]; // P lo

// ---------------- helpers ---------------------------------------------------
__device__ __forceinline__ uint32_t smem_u32(const void* p) {
    uint32_t a;
    asm("{ .reg .u64 t; cvta.to.shared.u64 t, %1; cvt.u32.u64 %0, t; }"
        : "=r"(a) : "l"(p));
    return a;
}
#define SW128(o) ((o) ^ (((o) >> 3) & 0x70))

__device__ __forceinline__ void ldm_x4(uint32_t* r, uint32_t addr) {
    asm volatile("ldmatrix.sync.aligned.m8n8.x4.shared.b16 {%0,%1,%2,%3}, [%4];"
                 : "=r"(r[0]), "=r"(r[1]), "=r"(r[2]), "=r"(r[3]) : "r"(addr));
}
__device__ __forceinline__ void mma_bf16(float* c, const uint32_t* a,
                                         uint32_t b0, uint32_t b1) {
    asm volatile(
        "mma.sync.aligned.m16n8k16.row.col.f32.bf16.bf16.f32 "
        "{%0,%1,%2,%3}, {%4,%5,%6,%7}, {%8,%9}, {%0,%1,%2,%3};"
        : "+f"(c[0]), "+f"(c[1]), "+f"(c[2]), "+f"(c[3])
        : "r"(a[0]), "r"(a[1]), "r"(a[2]), "r"(a[3]), "r"(b0), "r"(b1));
}
#define CP16(dst, src) \
    asm volatile("cp.async.cg.shared.global [%0], [%1], 16;" :: "r"(dst), "l"(src))
#define CP_COMMIT() asm volatile("cp.async.commit_group;")

// ---------------------------------------------------------------------------
// fp32 -> bf16 split-concat.  mode 0 (A): [hi,hi,lo]   mode 1 (B): [hi,lo,hi]
// ---------------------------------------------------------------------------
__global__ __launch_bounds__(256) void convert_cat(
    const float* __restrict__ src, __nv_bfloat16* __restrict__ dst,
    int rows, int mode)
{
    int n = rows * (DM / 4);
    for (int i = blockIdx.x * blockDim.x + threadIdx.x; i < n;
         i += gridDim.x * blockDim.x) {
        int r = i / (DM / 4), cq = i - r * (DM / 4);
        float4 v = *(const float4*)&src[(size_t)r * DM + cq * 4];
        float f[4] = {v.x, v.y, v.z, v.w};
        __nv_bfloat16 hi[4], lo[4];
#pragma unroll
        for (int j = 0; j < 4; j++) {
            hi[j] = __float2bfloat16(f[j]);
            lo[j] = __float2bfloat16(f[j] - __bfloat162float(hi[j]));
        }
        __nv_bfloat162 h01 = __halves2bfloat162(hi[0], hi[1]);
        __nv_bfloat162 h23 = __halves2bfloat162(hi[2], hi[3]);
        __nv_bfloat162 l01 = __halves2bfloat162(lo[0], lo[1]);
        __nv_bfloat162 l23 = __halves2bfloat162(lo[2], lo[3]);
        size_t base = (size_t)r * KCAT + cq * 4;
        __nv_bfloat162* d0 = (__nv_bfloat162*)&dst[base];
        __nv_bfloat162* d1 = (__nv_bfloat162*)&dst[base + DM];
        __nv_bfloat162* d2 = (__nv_bfloat162*)&dst[base + 2 * DM];
        d0[0] = h01; d0[1] = h23;
        if (mode == 0) { d1[0] = h01; d1[1] = h23; d2[0] = l01; d2[1] = l23; }
        else           { d1[0] = l01; d1[1] = l23; d2[0] = h01; d2[1] = h23; }
    }
}

// ---------------------------------------------------------------------------
// mma.sync bf16 GEMM: C[r,c] = sum_k A[r,k]*B[c,k] + bias[c]
// 3-stage cp.async pipeline (96KB smem) + forced 2 CTAs/SM.
// omode 0: fp32 row-major.  1: Q split A-layout.  2: K split B-layout.
// omode 3: V transposed hi/lo planes.
// ---------------------------------------------------------------------------
#define GEMM_SMEM 98304   // A: 3x16K at 0, B: 3x16K at 49152

__global__ void __launch_bounds__(256, 2) gemm_mma(
    const __nv_bfloat16* __restrict__ A, const __nv_bfloat16* __restrict__ B,
    const float* __restrict__ bias, float* __restrict__ outf,
    __nv_bfloat16* __restrict__ ob1, __nv_bfloat16* __restrict__ ob2, int omode)
{
    extern __shared__ __align__(1024) char smem[];
    const int tid = threadIdx.x;
    const int wid = tid >> 5, lane = tid & 31;
    const int warp_m = wid >> 2;
    const int warp_n = wid & 3;
    const uint32_t sb = smem_u32(smem);

    const int r0 = blockIdx.y * 128, c0 = blockIdx.x * 128;
    const int ls = tid & 7;
    const int lr = tid >> 3;

#define LOAD_STAGE(chunk, stage) do {                                          \
        uint32_t ab = sb + (stage) * 16384;                                    \
        uint32_t bb = sb + 49152 + (stage) * 16384;                            \
        size_t kb = (size_t)(chunk) * 64 + ls * 8;                             \
        _Pragma("unroll")                                                      \
        for (int i_ = 0; i_ < 4; i_++) {                                       \
            int r_ = lr + 32 * i_;                                             \
            uint32_t off = SW128(r_ * 128 + ls * 16);                          \
            CP16(ab + off, &A[(size_t)(r0 + r_) * KCAT + kb]);                 \
            CP16(bb + off, &B[(size_t)(c0 + r_) * KCAT + kb]);                 \
        }                                                                      \
        CP_COMMIT();                                                           \
    } while (0)

    float acc[4][4][4] = {};
    LOAD_STAGE(0, 0);
    LOAD_STAGE(1, 1);

    int st = 0;              // c % 3
    int st2 = 2;             // (c+2) % 3
    for (int c = 0; c < NKCH; c++) {
        if (c + 2 < NKCH) LOAD_STAGE(c + 2, st2);
        else              CP_COMMIT();
        asm volatile("cp.async.wait_group 2;");
        __syncthreads();

        const uint32_t abase = sb + st * 16384;
        const uint32_t bbase = sb + 49152 + st * 16384;
#pragma unroll
        for (int ks = 0; ks < 4; ks++) {
            uint32_t af[4][4];
#pragma unroll
            for (int mt = 0; mt < 4; mt++) {
                int row = warp_m * 64 + mt * 16 + (lane & 15);
                int seg = ks * 2 + (lane >> 4);
                ldm_x4(af[mt], abase + SW128(row * 128 + seg * 16));
            }
            uint32_t bf[2][4];
#pragma unroll
            for (int h = 0; h < 2; h++) {
                int row = warp_n * 32 + h * 16 + ((lane >> 4) & 1) * 8 + (lane & 7);
                int seg = ks * 2 + ((lane >> 3) & 1);
                ldm_x4(bf[h], bbase + SW128(row * 128 + seg * 16));
            }
#pragma unroll
            for (int mt = 0; mt < 4; mt++)
#pragma unroll
                for (int nt = 0; nt < 4; nt++)
                    mma_bf16(acc[mt][nt], af[mt],
                             bf[nt >> 1][(nt & 1) * 2], bf[nt >> 1][(nt & 1) * 2 + 1]);
        }
        __syncthreads();    // protect stage st from next iteration's load
        st  = (st  == 2) ? 0 : st + 1;
        st2 = (st2 == 2) ? 0 : st2 + 1;
    }
#undef LOAD_STAGE

    const int mrow = lane >> 2;
    const int ncol = 2 * (lane & 3);
#pragma unroll
    for (int mt = 0; mt < 4; mt++) {
#pragma unroll
        for (int nt = 0; nt < 4; nt++) {
            int cg = c0 + warp_n * 32 + nt * 8 + ncol;
            float b0 = __ldg(&bias[cg]), b1 = __ldg(&bias[cg + 1]);
#pragma unroll
            for (int half = 0; half < 2; half++) {
                int r = r0 + warp_m * 64 + mt * 16 + mrow + half * 8;
                float v0 = acc[mt][nt][half * 2] + b0;
                float v1 = acc[mt][nt][half * 2 + 1] + b1;
                if (omode == 0) {
                    float2 v = {v0, v1};
                    *(float2*)&outf[(size_t)r * DM + cg] = v;
                } else {
                    int bb = r >> 11, s = r & (S_LEN - 1);
                    int h = cg >> 6, hd = cg & 63;
                    __nv_bfloat16 h0 = __float2bfloat16(v0);
                    __nv_bfloat16 h1 = __float2bfloat16(v1);
                    __nv_bfloat16 l0 = __float2bfloat16(v0 - __bfloat162float(h0));
                    __nv_bfloat16 l1 = __float2bfloat16(v1 - __bfloat162float(h1));
                    __nv_bfloat162 hh = __halves2bfloat162(h0, h1);
                    __nv_bfloat162 ll = __halves2bfloat162(l0, l1);
                    if (omode == 3) {
                        size_t pb = ((size_t)(bb * NH + h) * HD + hd) * S_LEN + s;
                        ob1[pb] = h0; ob1[pb + S_LEN] = h1;
                        ob2[pb] = l0; ob2[pb + S_LEN] = l1;
                    } else {
                        size_t base = ((size_t)(bb * NH + h) * S_LEN + s) * KQK + hd;
                        *(__nv_bfloat162*)&ob1[base] = hh;
                        if (omode == 1) {
                            *(__nv_bfloat162*)&ob1[base + HD] = hh;
                            *(__nv_bfloat162*)&ob1[base + 2 * HD] = ll;
                        } else {
                            *(__nv_bfloat162*)&ob1[base + HD] = ll;
                            *(__nv_bfloat162*)&ob1[base + 2 * HD] = hh;
                        }
                    }
                }
            }
        }
    }
}

// ---------------------------------------------------------------------------
// scores_mma: attn[bh,q,k] = 0.125 * sum Q*K  via bf16 split (K'=192)
// ---------------------------------------------------------------------------
#define SC_SMEM 65536

__global__ __launch_bounds__(256) void scores_mma(
    const __nv_bfloat16* __restrict__ Qc, const __nv_bfloat16* __restrict__ Kc,
    float* __restrict__ attn)
{
    const int kt = blockIdx.x, qt = blockIdx.y, bh = blockIdx.z;
    if (kt > qt) return;
    extern __shared__ __align__(1024) char smem[];
    const int tid = threadIdx.x;
    const int wid = tid >> 5, lane = tid & 31;
    const int warp_m = wid >> 2;
    const int warp_n = wid & 3;
    const uint32_t sb = smem_u32(smem);
    const int q0 = qt * 128, c0 = kt * 128;

    const __nv_bfloat16* Ab = Qc + (size_t)bh * S_LEN * KQK;
    const __nv_bfloat16* Bb = Kc + (size_t)bh * S_LEN * KQK;
    const int ls = tid & 7;
    const int lr = tid >> 3;

#define SC_LOAD(chunk, stage) do {                                             \
        uint32_t ab = sb + (stage) * 16384;                                    \
        uint32_t bb = sb + 32768 + (stage) * 16384;                            \
        size_t kb = (size_t)(chunk) * 64 + ls * 8;                             \
        _Pragma("unroll")                                                      \
        for (int i_ = 0; i_ < 4; i_++) {                                       \
            int r_ = lr + 32 * i_;                                             \
            uint32_t off = SW128(r_ * 128 + ls * 16);                          \
            CP16(ab + off, &Ab[(size_t)(q0 + r_) * KQK + kb]);                 \
            CP16(bb + off, &Bb[(size_t)(c0 + r_) * KQK + kb]);                 \
        }                                                                      \
        CP_COMMIT();                                                           \
    } while (0)

    float acc[4][4][4] = {};
    SC_LOAD(0, 0);
    for (int c = 0; c < 3; c++) {
        const int st = c & 1;
        if (c + 1 < 3) {
            SC_LOAD(c + 1, st ^ 1);
            asm volatile("cp.async.wait_group 1;");
        } else {
            asm volatile("cp.async.wait_group 0;");
        }
        __syncthreads();
        const uint32_t abase = sb + st * 16384;
        const uint32_t bbase = sb + 32768 + st * 16384;
#pragma unroll
        for (int ks = 0; ks < 4; ks++) {
            uint32_t af[4][4];
#pragma unroll
            for (int mt = 0; mt < 4; mt++) {
                int row = warp_m * 64 + mt * 16 + (lane & 15);
                int seg = ks * 2 + (lane >> 4);
                ldm_x4(af[mt], abase + SW128(row * 128 + seg * 16));
            }
            uint32_t bf[2][4];
#pragma unroll
            for (int h = 0; h < 2; h++) {
                int row = warp_n * 32 + h * 16 + ((lane >> 4) & 1) * 8 + (lane & 7);
                int seg = ks * 2 + ((lane >> 3) & 1);
                ldm_x4(bf[h], bbase + SW128(row * 128 + seg * 16));
            }
#pragma unroll
            for (int mt = 0; mt < 4; mt++)
#pragma unroll
                for (int nt = 0; nt < 4; nt++)
                    mma_bf16(acc[mt][nt], af[mt],
                             bf[nt >> 1][(nt & 1) * 2], bf[nt >> 1][(nt & 1) * 2 + 1]);
        }
        __syncthreads();
    }
#undef SC_LOAD

    float* Arow = attn + (size_t)bh * S_LEN * S_LEN;
    const int mrow = lane >> 2;
    const int ncol = 2 * (lane & 3);
#pragma unroll
    for (int mt = 0; mt < 4; mt++)
#pragma unroll
        for (int nt = 0; nt < 4; nt++) {
            int cg = c0 + warp_n * 32 + nt * 8 + ncol;
#pragma unroll
            for (int half = 0; half < 2; half++) {
                int q = q0 + warp_m * 64 + mt * 16 + mrow + half * 8;
                float2 v = {acc[mt][nt][half * 2] * 0.125f,
                            acc[mt][nt][half * 2 + 1] * 0.125f};
                *(float2*)&Arow[(size_t)q * S_LEN + cg] = v;
            }
        }
}

// ---------------------------------------------------------------------------
// Row-wise causal softmax; writes fp32 probs (full row, covers poison) + bf16
// hi/lo planes ONLY up to the 128-row tile's k boundary (all av_mma reads).
// ---------------------------------------------------------------------------
__global__ __launch_bounds__(256) void softmax_kernel(
    float* __restrict__ attn, __nv_bfloat16* __restrict__ Ph,
    __nv_bfloat16* __restrict__ Pl)
{
    const int q = blockIdx.x, bh = blockIdx.y;
    const size_t rbase = ((size_t)bh * S_LEN + q) * S_LEN;
    float* row = attn + rbase;
    const int tid = threadIdx.x;
    const int valid = q + 1;
    const int tile_kend = (q & ~127) + 128;     // av tile boundary
    const int b0 = 4 * tid, b1 = 4 * (tid + 256);

    float4 v0 = {-INFINITY, -INFINITY, -INFINITY, -INFINITY}, v1 = v0;
    if (b0 < valid) v0 = *(const float4*)&row[b0];
    if (b1 < valid) v1 = *(const float4*)&row[b1];
    float vals[8] = {v0.x, v0.y, v0.z, v0.w, v1.x, v1.y, v1.z, v1.w};

    float mx = -INFINITY;
#pragma unroll
    for (int i = 0; i < 8; i++) {
        int k = (i < 4) ? (b0 + i) : (b1 + i - 4);
        if (k >= valid) vals[i] = -INFINITY;
        mx = fmaxf(mx, vals[i]);
    }
#pragma unroll
    for (int o = 16; o; o >>= 1) mx = fmaxf(mx, __shfl_xor_sync(~0u, mx, o));
    __shared__ float sred[8];
    if ((tid & 31) == 0) sred[tid >> 5] = mx;
    __syncthreads();
    mx = sred[0];
#pragma unroll
    for (int i = 1; i < 8; i++) mx = fmaxf(mx, sred[i]);
    __syncthreads();

    float sum = 0.f;
#pragma unroll
    for (int i = 0; i < 8; i++) {
        float e = __expf(vals[i] - mx);
        vals[i] = e;
        sum += e;
    }
#pragma unroll
    for (int o = 16; o; o >>= 1) sum += __shfl_xor_sync(~0u, sum, o);
    if ((tid & 31) == 0) sred[tid >> 5] = sum;
    __syncthreads();
    sum = 0.f;
#pragma unroll
    for (int i = 0; i < 8; i++) sum += sred[i];
    const float inv = 1.f / sum;

    float p[8];
    __nv_bfloat16 hh[8], ll[8];
#pragma unroll
    for (int i = 0; i < 8; i++) {
        p[i] = vals[i] * inv;
        hh[i] = __float2bfloat16(p[i]);
        ll[i] = __float2bfloat16(p[i] - __bfloat162float(hh[i]));
    }
    float4 w0 = {p[0], p[1], p[2], p[3]};
    float4 w1 = {p[4], p[5], p[6], p[7]};
    *(float4*)&row[b0] = w0;
    *(float4*)&row[b1] = w1;
    if (b0 < tile_kend) {
#pragma unroll
        for (int j = 0; j < 2; j++) {
            *(__nv_bfloat162*)&Ph[rbase + b0 + 2*j] = __halves2bfloat162(hh[2*j], hh[2*j+1]);
            *(__nv_bfloat162*)&Pl[rbase + b0 + 2*j] = __halves2bfloat162(ll[2*j], ll[2*j+1]);
        }
    }
    if (b1 < tile_kend) {
#pragma unroll
        for (int j = 0; j < 2; j++) {
            *(__nv_bfloat162*)&Ph[rbase + b1 + 2*j] = __halves2bfloat162(hh[4+2*j], hh[5+2*j]);
            *(__nv_bfloat162*)&Pl[rbase + b1 + 2*j] = __halves2bfloat162(ll[4+2*j], ll[5+2*j]);
        }
    }
}

// ---------------------------------------------------------------------------
// av_mma: A[q,hd] = sum_k P[q,k]*V[k,hd] via Ph*Vh + Pl*Vh + Ph*Vl.
// 128(q) x 64(hd) tile; causal chunk bound. Writes A in split-cat layout.
// ---------------------------------------------------------------------------
#define AV_SMEM 98304

__global__ __launch_bounds__(256) void av_mma(
    const __nv_bfloat16* __restrict__ Ph, const __nv_bfloat16* __restrict__ Pl,
    const __nv_bfloat16* __restrict__ Vth, const __nv_bfloat16* __restrict__ Vtl,
    __nv_bfloat16* __restrict__ Acat)
{
    const int qt = blockIdx.x, bh = blockIdx.y;
    extern __shared__ __align__(1024) char smem[];
    const int tid = threadIdx.x;
    const int wid = tid >> 5, lane = tid & 31;
    const int warp_m = wid & 3;           // 32 q rows each
    const int warp_n = wid >> 2;          // 32 hd cols each
    const uint32_t sb = smem_u32(smem);
    const int q0 = qt * 128;

    const __nv_bfloat16* Phb = Ph + (size_t)bh * S_LEN * S_LEN;
    const __nv_bfloat16* Plb = Pl + (size_t)bh * S_LEN * S_LEN;
    const __nv_bfloat16* Vhb = Vth + (size_t)bh * HD * S_LEN;
    const __nv_bfloat16* Vlb = Vtl + (size_t)bh * HD * S_LEN;

    const int ls = tid & 7;
    const int lr = tid >> 3;
    const int nch = (q0 + 128) / 64;

#define AV_LOAD(chunk, stage) do {                                             \
        uint32_t base = sb + (stage) * 49152;                                  \
        size_t kb = (size_t)(chunk) * 64 + ls * 8;                             \
        _Pragma("unroll")                                                      \
        for (int i_ = 0; i_ < 4; i_++) {                                       \
            int r_ = lr + 32 * i_;                                             \
            uint32_t off = SW128(r_ * 128 + ls * 16);                          \
            CP16(base + off,         &Phb[(size_t)(q0 + r_) * S_LEN + kb]);    \
            CP16(base + 16384 + off, &Plb[(size_t)(q0 + r_) * S_LEN + kb]);    \
        }                                                                      \
        _Pragma("unroll")                                                      \
        for (int i_ = 0; i_ < 2; i_++) {                                       \
            int r_ = lr + 32 * i_;                                             \
            uint32_t off = SW128(r_ * 128 + ls * 16);                          \
            CP16(base + 32768 + off, &Vhb[(size_t)r_ * S_LEN + kb]);           \
            CP16(base + 40960 + off, &Vlb[(size_t)r_ * S_LEN + kb]);           \
        }                                                                      \
        CP_COMMIT();                                                           \
    } while (0)

    float acc[2][4][4] = {};
    AV_LOAD(0, 0);
    for (int c = 0; c < nch; c++) {
        const int st = c & 1;
        if (c + 1 < nch) {
            AV_LOAD(c + 1, st ^ 1);
            asm volatile("cp.async.wait_group 1;");
        } else {
            asm volatile("cp.async.wait_group 0;");
        }
        __syncthreads();
        const uint32_t base = sb + st * 49152;
#pragma unroll
        for (int ks = 0; ks < 4; ks++) {
            uint32_t ah[2][4], al[2][4];
#pragma unroll
            for (int mt = 0; mt < 2; mt++) {
                int row = warp_m * 32 + mt * 16 + (lane & 15);
                int seg = ks * 2 + (lane >> 4);
                uint32_t off = SW128(row * 128 + seg * 16);
                ldm_x4(ah[mt], base + off);
                ldm_x4(al[mt], base + 16384 + off);
            }
            uint32_t bh_[2][4], bl_[2][4];
#pragma unroll
            for (int h = 0; h < 2; h++) {
                int row = warp_n * 32 + h * 16 + ((lane >> 4) & 1) * 8 + (lane & 7);
                int seg = ks * 2 + ((lane >> 3) & 1);
                uint32_t off = SW128(row * 128 + seg * 16);
                ldm_x4(bh_[h], base + 32768 + off);
                ldm_x4(bl_[h], base + 40960 + off);
            }
#pragma unroll
            for (int mt = 0; mt < 2; mt++)
#pragma unroll
                for (int nt = 0; nt < 4; nt++) {
                    uint32_t vh0 = bh_[nt >> 1][(nt & 1) * 2];
                    uint32_t vh1 = bh_[nt >> 1][(nt & 1) * 2 + 1];
                    uint32_t vl0 = bl_[nt >> 1][(nt & 1) * 2];
                    uint32_t vl1 = bl_[nt >> 1][(nt & 1) * 2 + 1];
                    mma_bf16(acc[mt][nt], ah[mt], vh0, vh1);
                    mma_bf16(acc[mt][nt], al[mt], vh0, vh1);
                    mma_bf16(acc[mt][nt], ah[mt], vl0, vl1);
                }
        }
        __syncthreads();
    }
#undef AV_LOAD

    // epilogue: write A in split-cat layout [hi,hi,lo] for the Wo GEMM
    const int bb = bh / NH, h = bh % NH;
    const int mrow = lane >> 2;
    const int ncol = 2 * (lane & 3);
#pragma unroll
    for (int mt = 0; mt < 2; mt++)
#pragma unroll
        for (int nt = 0; nt < 4; nt++) {
            int hd = warp_n * 32 + nt * 8 + ncol;
            int cc = h * HD + hd;
#pragma unroll
            for (int half = 0; half < 2; half++) {
                int s = q0 + warp_m * 32 + mt * 16 + mrow + half * 8;
                float v0 = acc[mt][nt][half * 2];
                float v1 = acc[mt][nt][half * 2 + 1];
                __nv_bfloat16 h0 = __float2bfloat16(v0);
                __nv_bfloat16 h1 = __float2bfloat16(v1);
                __nv_bfloat16 l0 = __float2bfloat16(v0 - __bfloat162float(h0));
                __nv_bfloat16 l1 = __float2bfloat16(v1 - __bfloat162float(h1));
                size_t base = ((size_t)(bb * S_LEN + s)) * KCAT + cc;
                *(__nv_bfloat162*)&Acat[base]          = __halves2bfloat162(h0, h1);
                *(__nv_bfloat162*)&Acat[base + DM]     = __halves2bfloat162(h0, h1);
                *(__nv_bfloat162*)&Acat[base + 2 * DM] = __halves2bfloat162(l0, l1);
            }
        }
}

// ---------------------------------------------------------------------------
extern "C" void kernel_launch(void* const* d_in, const int* in_sizes, int n_in,
                              void* d_out, int out_size)
{
    const float* X  = (const float*)d_in[0];
    const float* Wq = (const float*)d_in[1];
    const float* bq = (const float*)d_in[2];
    const float* Wk = (const float*)d_in[3];
    const float* bk = (const float*)d_in[4];
    const float* Wv = (const float*)d_in[5];
    const float* bv = (const float*)d_in[6];
    const float* Wo = (const float*)d_in[7];
    const float* bo = (const float*)d_in[8];

    float* out  = (float*)d_out;
    float* attn = out + (size_t)MROWS * DM;

    __nv_bfloat16 *gXc, *gAc, *gWq, *gWk, *gWv, *gWo;
    __nv_bfloat16 *gQc, *gKc, *gVh, *gVl, *gPh, *gPl;
    cudaGetSymbolAddress((void**)&gXc, g_Xcat);
    cudaGetSymbolAddress((void**)&gAc, g_Acat);
    cudaGetSymbolAddress((void**)&gWq, g_Wqc);
    cudaGetSymbolAddress((void**)&gWk, g_Wkc);
    cudaGetSymbolAddress((void**)&gWv, g_Wvc);
    cudaGetSymbolAddress((void**)&gWo, g_Woc);
    cudaGetSymbolAddress((void**)&gQc, g_Qc);
    cudaGetSymbolAddress((void**)&gKc, g_Kc);
    cudaGetSymbolAddress((void**)&gVh, g_Vth);
    cudaGetSymbolAddress((void**)&gVl, g_Vtl);
    cudaGetSymbolAddress((void**)&gPh, g_Ph);
    cudaGetSymbolAddress((void**)&gPl, g_Pl);

    static cudaStream_t s1, s2, s3;
    static cudaEvent_t evRoot, evX, ev1, ev2, ev3;
    static int init_done = 0;
    if (!init_done) {
        cudaFuncSetAttribute(gemm_mma, cudaFuncAttributeMaxDynamicSharedMemorySize, GEMM_SMEM);
        cudaFuncSetAttribute(scores_mma, cudaFuncAttributeMaxDynamicSharedMemorySize, SC_SMEM);
        cudaFuncSetAttribute(av_mma, cudaFuncAttributeMaxDynamicSharedMemorySize, AV_SMEM);
        cudaStreamCreateWithFlags(&s1, cudaStreamNonBlocking);
        cudaStreamCreateWithFlags(&s2, cudaStreamNonBlocking);
        cudaStreamCreateWithFlags(&s3, cudaStreamNonBlocking);
        cudaEventCreateWithFlags(&evRoot, cudaEventDisableTiming);
        cudaEventCreateWithFlags(&evX, cudaEventDisableTiming);
        cudaEventCreateWithFlags(&ev1, cudaEventDisableTiming);
        cudaEventCreateWithFlags(&ev2, cudaEventDisableTiming);
        cudaEventCreateWithFlags(&ev3, cudaEventDisableTiming);
        init_done = 1;
    }

    dim3 blk(256);
    dim3 ggemm(DM / 128, MROWS / 128);

    // fork side streams off the capture-origin stream
    cudaEventRecord(evRoot, 0);
    cudaStreamWaitEvent(s1, evRoot, 0);
    cudaStreamWaitEvent(s2, evRoot, 0);
    cudaStreamWaitEvent(s3, evRoot, 0);

    // main: X convert (feeds all three projection GEMMs)
    convert_cat<<<1024, blk, 0, 0>>>(X, gXc, MROWS, 0);
    cudaEventRecord(evX, 0);
    // main: Wo convert overlaps the QKV GEMMs on the side streams
    convert_cat<<<512, blk, 0, 0>>>(Wo, gWo, DM, 1);

    // s1: Wq convert -> Q GEMM
    convert_cat<<<512, blk, 0, s1>>>(Wq, gWq, DM, 1);
    cudaStreamWaitEvent(s1, evX, 0);
    gemm_mma<<<ggemm, blk, GEMM_SMEM, s1>>>(gXc, gWq, bq, nullptr, gQc, nullptr, 1);
    cudaEventRecord(ev1, s1);

    // s2: Wk convert -> K GEMM
    convert_cat<<<512, blk, 0, s2>>>(Wk, gWk, DM, 1);
    cudaStreamWaitEvent(s2, evX, 0);
    gemm_mma<<<ggemm, blk, GEMM_SMEM, s2>>>(gXc, gWk, bk, nullptr, gKc, nullptr, 2);
    cudaEventRecord(ev2, s2);

    // s3: Wv convert -> V GEMM
    convert_cat<<<512, blk, 0, s3>>>(Wv, gWv, DM, 1);
    cudaStreamWaitEvent(s3, evX, 0);
    gemm_mma<<<ggemm, blk, GEMM_SMEM, s3>>>(gXc, gWv, bv, nullptr, gVh, gVl, 3);
    cudaEventRecord(ev3, s3);

    // main: scores needs Q (ev1) and K (ev2)
    cudaStreamWaitEvent(0, ev1, 0);
    cudaStreamWaitEvent(0, ev2, 0);
    dim3 gsc(S_LEN / 128, S_LEN / 128, BHN);
    scores_mma<<<gsc, blk, SC_SMEM, 0>>>(gQc, gKc, attn);

    dim3 gsm(S_LEN, BHN);
    softmax_kernel<<<gsm, blk, 0, 0>>>(attn, gPh, gPl);

    // av needs V (ev3)
    cudaStreamWaitEvent(0, ev3, 0);
    dim3 gav(S_LEN / 128, BHN);
    av_mma<<<gav, blk, AV_SMEM, 0>>>(gPh, gPl, gVh, gVl, gAc);

    gemm_mma<<<ggemm, blk, GEMM_SMEM, 0>>>(gAc, gWo, bo, out, nullptr, nullptr, 0);
}

// round 9
// speedup vs baseline: 1.8005x; 1.1129x over previous
#include <cuda_runtime.h>
#include <cuda_bf16.h>
#include <math.h>
#include <stdint.h>

#define S_LEN 2048
#define DM    1024
#define NH    16
#define HD    64
#define BATCH 2
#define BHN   (BATCH * NH)        // 32
#define MROWS (BATCH * S_LEN)     // 4096
#define KC2   2048                // [hi|lo] interleaved per 32-k chunk
#define NCH2  32                  // 32 chunks of 32 k-elems
#define QK2   128                 // Q/K row: [hi 64 | lo 64]

// ---------------- scratch (__device__ globals) ------------------------------
__device__ __nv_bfloat16 g_Xcat[(size_t)MROWS * KC2];
__device__ __nv_bfloat16 g_Acat[(size_t)MROWS * KC2];
__device__ __nv_bfloat16 g_Wqc[(size_t)DM * KC2];
__device__ __nv_bfloat16 g_Wkc[(size_t)DM * KC2];
__device__ __nv_bfloat16 g_Wvc[(size_t)DM * KC2];
__device__ __nv_bfloat16 g_Woc[(size_t)DM * KC2];
__device__ __nv_bfloat16 g_Qc[(size_t)BHN * S_LEN * QK2];   // [hi|lo]
__device__ __nv_bfloat16 g_Kc[(size_t)BHN * S_LEN * QK2];   // [hi|lo]
__device__ __nv_bfloat16 g_Vth[(size_t)BHN * HD * S_LEN];   // V^T hi
__device__ __nv_bfloat16 g_Vtl[(size_t)BHN * HD * S_LEN];   // V^T lo
__device__ __nv_bfloat16 g_Ph[(size_t)BHN * S_LEN * S_LEN]; // P hi
__device__ __nv_bfloat16 g_Pl[(size_t)BHN * S_LEN * S_LEN]; // P lo

// ---------------- helpers ---------------------------------------------------
__device__ __forceinline__ uint32_t smem_u32(const void* p) {
    uint32_t a;
    asm("{ .reg .u64 t; cvta.to.shared.u64 t, %1; cvt.u32.u64 %0, t; }"
        : "=r"(a) : "l"(p));
    return a;
}
#define SW128(o) ((o) ^ (((o) >> 3) & 0x70))

__device__ __forceinline__ void ldm_x4(uint32_t* r, uint32_t addr) {
    asm volatile("ldmatrix.sync.aligned.m8n8.x4.shared.b16 {%0,%1,%2,%3}, [%4];"
                 : "=r"(r[0]), "=r"(r[1]), "=r"(r[2]), "=r"(r[3]) : "r"(addr));
}
__device__ __forceinline__ void mma_bf16(float* c, const uint32_t* a,
                                         uint32_t b0, uint32_t b1) {
    asm volatile(
        "mma.sync.aligned.m16n8k16.row.col.f32.bf16.bf16.f32 "
        "{%0,%1,%2,%3}, {%4,%5,%6,%7}, {%8,%9}, {%0,%1,%2,%3};"
        : "+f"(c[0]), "+f"(c[1]), "+f"(c[2]), "+f"(c[3])
        : "r"(a[0]), "r"(a[1]), "r"(a[2]), "r"(a[3]), "r"(b0), "r"(b1));
}
#define CP16(dst, src) \
    asm volatile("cp.async.cg.shared.global [%0], [%1], 16;" :: "r"(dst), "l"(src))
#define CP_COMMIT() asm volatile("cp.async.commit_group;")

// ---------------------------------------------------------------------------
// fp32 [rows,1024] -> bf16 [rows,2048], per-32-chunk interleave [hi32|lo32].
// ---------------------------------------------------------------------------
__global__ __launch_bounds__(256) void convert_cat(
    const float* __restrict__ src, __nv_bfloat16* __restrict__ dst, int rows)
{
    int n = rows * (DM / 4);
    for (int i = blockIdx.x * blockDim.x + threadIdx.x; i < n;
         i += gridDim.x * blockDim.x) {
        int r = i / (DM / 4), cq = i - r * (DM / 4);
        float4 v = *(const float4*)&src[(size_t)r * DM + cq * 4];
        float f[4] = {v.x, v.y, v.z, v.w};
        __nv_bfloat16 hi[4], lo[4];
#pragma unroll
        for (int j = 0; j < 4; j++) {
            hi[j] = __float2bfloat16(f[j]);
            lo[j] = __float2bfloat16(f[j] - __bfloat162float(hi[j]));
        }
        int c = cq >> 3;             // chunk (32 k-elems = 8 quads)
        int p = (cq & 7) * 4;        // pos in chunk
        size_t base = (size_t)r * KC2 + c * 64 + p;
        *(__nv_bfloat162*)&dst[base]      = __halves2bfloat162(hi[0], hi[1]);
        *(__nv_bfloat162*)&dst[base + 2]  = __halves2bfloat162(hi[2], hi[3]);
        *(__nv_bfloat162*)&dst[base + 32] = __halves2bfloat162(lo[0], lo[1]);
        *(__nv_bfloat162*)&dst[base + 34] = __halves2bfloat162(lo[2], lo[3]);
    }
}

// ---------------------------------------------------------------------------
// mma.sync bf16 GEMM: C[r,c] = sum_k A[r,k]*B[c,k] + bias[c]
// Operands [rows, 2048] interleaved [hi|lo] per 32-chunk. Per chunk: 3 passes
// Ah*Bh + Ah*Bl + Al*Bh with fragment reuse. 3-stage cp.async, 2 CTAs/SM.
// omode 0: fp32 row-major.  1: Q/K split [hi|lo].  3: V^T hi/lo planes.
// ---------------------------------------------------------------------------
#define GEMM_SMEM 98304   // A: 3x16K at 0, B: 3x16K at 49152

__global__ void __launch_bounds__(256, 2) gemm_mma(
    const __nv_bfloat16* __restrict__ A, const __nv_bfloat16* __restrict__ B,
    const float* __restrict__ bias, float* __restrict__ outf,
    __nv_bfloat16* __restrict__ ob1, __nv_bfloat16* __restrict__ ob2, int omode)
{
    extern __shared__ __align__(1024) char smem[];
    const int tid = threadIdx.x;
    const int wid = tid >> 5, lane = tid & 31;
    const int warp_m = wid >> 2;
    const int warp_n = wid & 3;
    const uint32_t sb = smem_u32(smem);

    const int r0 = blockIdx.y * 128, c0 = blockIdx.x * 128;
    const int ls = tid & 7;
    const int lr = tid >> 3;

    // one stage tile = 128 rows x 128B ([hi32|lo32] bf16) per operand
#define LOAD_STAGE(chunk, stage) do {                                          \
        uint32_t ab = sb + (stage) * 16384;                                    \
        uint32_t bb = sb + 49152 + (stage) * 16384;                            \
        size_t kb = (size_t)(chunk) * 64 + ls * 8;                             \
        _Pragma("unroll")                                                      \
        for (int i_ = 0; i_ < 4; i_++) {                                       \
            int r_ = lr + 32 * i_;                                             \
            uint32_t off = SW128(r_ * 128 + ls * 16);                          \
            CP16(ab + off, &A[(size_t)(r0 + r_) * KC2 + kb]);                  \
            CP16(bb + off, &B[(size_t)(c0 + r_) * KC2 + kb]);                  \
        }                                                                      \
        CP_COMMIT();                                                           \
    } while (0)

    float acc[4][4][4] = {};
    LOAD_STAGE(0, 0);
    LOAD_STAGE(1, 1);

    int st = 0, st2 = 2;
    for (int c = 0; c < NCH2; c++) {
        if (c + 2 < NCH2) LOAD_STAGE(c + 2, st2);
        else              CP_COMMIT();
        asm volatile("cp.async.wait_group 2;");
        __syncthreads();

        const uint32_t abase = sb + st * 16384;
        const uint32_t bbase = sb + 49152 + st * 16384;
#pragma unroll
        for (int ks = 0; ks < 2; ks++) {           // 2 x k16 per 32-chunk
            uint32_t af[4][4];
            uint32_t bh[2][4], bl[2][4];
#pragma unroll
            for (int mt = 0; mt < 4; mt++) {       // A-hi frags
                int row = warp_m * 64 + mt * 16 + (lane & 15);
                int seg = ks * 2 + (lane >> 4);
                ldm_x4(af[mt], abase + SW128(row * 128 + seg * 16));
            }
#pragma unroll
            for (int h = 0; h < 2; h++) {          // B-hi / B-lo frags
                int row = warp_n * 32 + h * 16 + ((lane >> 4) & 1) * 8 + (lane & 7);
                int seg = ks * 2 + ((lane >> 3) & 1);
                uint32_t off = row * 128 + seg * 16;
                ldm_x4(bh[h], bbase + SW128(off));
                ldm_x4(bl[h], bbase + SW128(off + 64));   // lo half of row
            }
#pragma unroll
            for (int mt = 0; mt < 4; mt++)         // Ah*Bh
#pragma unroll
                for (int nt = 0; nt < 4; nt++)
                    mma_bf16(acc[mt][nt], af[mt],
                             bh[nt >> 1][(nt & 1) * 2], bh[nt >> 1][(nt & 1) * 2 + 1]);
#pragma unroll
            for (int mt = 0; mt < 4; mt++)         // Ah*Bl
#pragma unroll
                for (int nt = 0; nt < 4; nt++)
                    mma_bf16(acc[mt][nt], af[mt],
                             bl[nt >> 1][(nt & 1) * 2], bl[nt >> 1][(nt & 1) * 2 + 1]);
#pragma unroll
            for (int mt = 0; mt < 4; mt++) {       // reuse regs: A-lo frags
                int row = warp_m * 64 + mt * 16 + (lane & 15);
                int seg = 4 + ks * 2 + (lane >> 4);
                ldm_x4(af[mt], abase + SW128(row * 128 + seg * 16));
            }
#pragma unroll
            for (int mt = 0; mt < 4; mt++)         // Al*Bh
#pragma unroll
                for (int nt = 0; nt < 4; nt++)
                    mma_bf16(acc[mt][nt], af[mt],
                             bh[nt >> 1][(nt & 1) * 2], bh[nt >> 1][(nt & 1) * 2 + 1]);
        }
        __syncthreads();
        st  = (st  == 2) ? 0 : st + 1;
        st2 = (st2 == 2) ? 0 : st2 + 1;
    }
#undef LOAD_STAGE

    const int mrow = lane >> 2;
    const int ncol = 2 * (lane & 3);
#pragma unroll
    for (int mt = 0; mt < 4; mt++) {
#pragma unroll
        for (int nt = 0; nt < 4; nt++) {
            int cg = c0 + warp_n * 32 + nt * 8 + ncol;
            float b0 = __ldg(&bias[cg]), b1 = __ldg(&bias[cg + 1]);
#pragma unroll
            for (int half = 0; half < 2; half++) {
                int r = r0 + warp_m * 64 + mt * 16 + mrow + half * 8;
                float v0 = acc[mt][nt][half * 2] + b0;
                float v1 = acc[mt][nt][half * 2 + 1] + b1;
                if (omode == 0) {
                    float2 v = {v0, v1};
                    *(float2*)&outf[(size_t)r * DM + cg] = v;
                } else {
                    int bb = r >> 11, s = r & (S_LEN - 1);
                    int h = cg >> 6, hd = cg & 63;
                    __nv_bfloat16 h0 = __float2bfloat16(v0);
                    __nv_bfloat16 h1 = __float2bfloat16(v1);
                    __nv_bfloat16 l0 = __float2bfloat16(v0 - __bfloat162float(h0));
                    __nv_bfloat16 l1 = __float2bfloat16(v1 - __bfloat162float(h1));
                    if (omode == 3) {
                        size_t pb = ((size_t)(bb * NH + h) * HD + hd) * S_LEN + s;
                        ob1[pb] = h0; ob1[pb + S_LEN] = h1;
                        ob2[pb] = l0; ob2[pb + S_LEN] = l1;
                    } else {   // omode 1: Q/K [hi|lo] rows of 128
                        size_t base = ((size_t)(bb * NH + h) * S_LEN + s) * QK2 + hd;
                        *(__nv_bfloat162*)&ob1[base]      = __halves2bfloat162(h0, h1);
                        *(__nv_bfloat162*)&ob1[base + 64] = __halves2bfloat162(l0, l1);
                    }
                }
            }
        }
    }
}

// ---------------------------------------------------------------------------
// scores_mma: attn = 0.125 * (Qh*Kh + Qh*Kl + Ql*Kh).  Q/K rows [hi|lo] (128).
// Single-shot 64KB tile: Qh@0, Ql@16K, Kh@32K, Kl@48K.
// ---------------------------------------------------------------------------
#define SC_SMEM 65536

__global__ __launch_bounds__(256) void scores_mma(
    const __nv_bfloat16* __restrict__ Qc, const __nv_bfloat16* __restrict__ Kc,
    float* __restrict__ attn)
{
    const int kt = blockIdx.x, qt = blockIdx.y, bh = blockIdx.z;
    if (kt > qt) return;
    extern __shared__ __align__(1024) char smem[];
    const int tid = threadIdx.x;
    const int wid = tid >> 5, lane = tid & 31;
    const int warp_m = wid >> 2;
    const int warp_n = wid & 3;
    const uint32_t sb = smem_u32(smem);
    const int q0 = qt * 128, c0 = kt * 128;

    const __nv_bfloat16* Qb = Qc + (size_t)bh * S_LEN * QK2;
    const __nv_bfloat16* Kb = Kc + (size_t)bh * S_LEN * QK2;
    const int ls = tid & 7;
    const int lr = tid >> 3;

    // load all four 16KB planes
#pragma unroll
    for (int i_ = 0; i_ < 4; i_++) {
        int r_ = lr + 32 * i_;
        uint32_t off = SW128(r_ * 128 + ls * 16);
        CP16(sb + off,         &Qb[(size_t)(q0 + r_) * QK2 + ls * 8]);
        CP16(sb + 16384 + off, &Qb[(size_t)(q0 + r_) * QK2 + 64 + ls * 8]);
        CP16(sb + 32768 + off, &Kb[(size_t)(c0 + r_) * QK2 + ls * 8]);
        CP16(sb + 49152 + off, &Kb[(size_t)(c0 + r_) * QK2 + 64 + ls * 8]);
    }
    CP_COMMIT();
    asm volatile("cp.async.wait_group 0;");
    __syncthreads();

    float acc[4][4][4] = {};
#pragma unroll
    for (int ks = 0; ks < 4; ks++) {
        uint32_t af[4][4], bh[2][4], bl[2][4];
#pragma unroll
        for (int mt = 0; mt < 4; mt++) {        // Q-hi frags
            int row = warp_m * 64 + mt * 16 + (lane & 15);
            int seg = ks * 2 + (lane >> 4);
            ldm_x4(af[mt], sb + SW128(row * 128 + seg * 16));
        }
#pragma unroll
        for (int h = 0; h < 2; h++) {           // K-hi / K-lo frags
            int row = warp_n * 32 + h * 16 + ((lane >> 4) & 1) * 8 + (lane & 7);
            int seg = ks * 2 + ((lane >> 3) & 1);
            uint32_t off = SW128(row * 128 + seg * 16);
            ldm_x4(bh[h], sb + 32768 + off);
            ldm_x4(bl[h], sb + 49152 + off);
        }
#pragma unroll
        for (int mt = 0; mt < 4; mt++)          // Qh*Kh
#pragma unroll
            for (int nt = 0; nt < 4; nt++)
                mma_bf16(acc[mt][nt], af[mt],
                         bh[nt >> 1][(nt & 1) * 2], bh[nt >> 1][(nt & 1) * 2 + 1]);
#pragma unroll
        for (int mt = 0; mt < 4; mt++)          // Qh*Kl
#pragma unroll
            for (int nt = 0; nt < 4; nt++)
                mma_bf16(acc[mt][nt], af[mt],
                         bl[nt >> 1][(nt & 1) * 2], bl[nt >> 1][(nt & 1) * 2 + 1]);
#pragma unroll
        for (int mt = 0; mt < 4; mt++) {        // Q-lo frags (reuse regs)
            int row = warp_m * 64 + mt * 16 + (lane & 15);
            int seg = ks * 2 + (lane >> 4);
            ldm_x4(af[mt], sb + 16384 + SW128(row * 128 + seg * 16));
        }
#pragma unroll
        for (int mt = 0; mt < 4; mt++)          // Ql*Kh
#pragma unroll
            for (int nt = 0; nt < 4; nt++)
                mma_bf16(acc[mt][nt], af[mt],
                         bh[nt >> 1][(nt & 1) * 2], bh[nt >> 1][(nt & 1) * 2 + 1]);
    }

    float* Arow = attn + (size_t)bh * S_LEN * S_LEN;
    const int mrow = lane >> 2;
    const int ncol = 2 * (lane & 3);
#pragma unroll
    for (int mt = 0; mt < 4; mt++)
#pragma unroll
        for (int nt = 0; nt < 4; nt++) {
            int cg = c0 + warp_n * 32 + nt * 8 + ncol;
#pragma unroll
            for (int half = 0; half < 2; half++) {
                int q = q0 + warp_m * 64 + mt * 16 + mrow + half * 8;
                float2 v = {acc[mt][nt][half * 2] * 0.125f,
                            acc[mt][nt][half * 2 + 1] * 0.125f};
                *(float2*)&Arow[(size_t)q * S_LEN + cg] = v;
            }
        }
}

// ---------------------------------------------------------------------------
// Row-wise causal softmax; fp32 probs (full row) + bf16 hi/lo planes clipped
// to the 128-row tile's k boundary.
// ---------------------------------------------------------------------------
__global__ __launch_bounds__(256) void softmax_kernel(
    float* __restrict__ attn, __nv_bfloat16* __restrict__ Ph,
    __nv_bfloat16* __restrict__ Pl)
{
    const int q = blockIdx.x, bh = blockIdx.y;
    const size_t rbase = ((size_t)bh * S_LEN + q) * S_LEN;
    float* row = attn + rbase;
    const int tid = threadIdx.x;
    const int valid = q + 1;
    const int tile_kend = (q & ~127) + 128;
    const int b0 = 4 * tid, b1 = 4 * (tid + 256);

    float4 v0 = {-INFINITY, -INFINITY, -INFINITY, -INFINITY}, v1 = v0;
    if (b0 < valid) v0 = *(const float4*)&row[b0];
    if (b1 < valid) v1 = *(const float4*)&row[b1];
    float vals[8] = {v0.x, v0.y, v0.z, v0.w, v1.x, v1.y, v1.z, v1.w};

    float mx = -INFINITY;
#pragma unroll
    for (int i = 0; i < 8; i++) {
        int k = (i < 4) ? (b0 + i) : (b1 + i - 4);
        if (k >= valid) vals[i] = -INFINITY;
        mx = fmaxf(mx, vals[i]);
    }
#pragma unroll
    for (int o = 16; o; o >>= 1) mx = fmaxf(mx, __shfl_xor_sync(~0u, mx, o));
    __shared__ float sred[8];
    if ((tid & 31) == 0) sred[tid >> 5] = mx;
    __syncthreads();
    mx = sred[0];
#pragma unroll
    for (int i = 1; i < 8; i++) mx = fmaxf(mx, sred[i]);
    __syncthreads();

    float sum = 0.f;
#pragma unroll
    for (int i = 0; i < 8; i++) {
        float e = __expf(vals[i] - mx);
        vals[i] = e;
        sum += e;
    }
#pragma unroll
    for (int o = 16; o; o >>= 1) sum += __shfl_xor_sync(~0u, sum, o);
    if ((tid & 31) == 0) sred[tid >> 5] = sum;
    __syncthreads();
    sum = 0.f;
#pragma unroll
    for (int i = 0; i < 8; i++) sum += sred[i];
    const float inv = 1.f / sum;

    float p[8];
    __nv_bfloat16 hh[8], ll[8];
#pragma unroll
    for (int i = 0; i < 8; i++) {
        p[i] = vals[i] * inv;
        hh[i] = __float2bfloat16(p[i]);
        ll[i] = __float2bfloat16(p[i] - __bfloat162float(hh[i]));
    }
    float4 w0 = {p[0], p[1], p[2], p[3]};
    float4 w1 = {p[4], p[5], p[6], p[7]};
    *(float4*)&row[b0] = w0;
    *(float4*)&row[b1] = w1;
    if (b0 < tile_kend) {
#pragma unroll
        for (int j = 0; j < 2; j++) {
            *(__nv_bfloat162*)&Ph[rbase + b0 + 2*j] = __halves2bfloat162(hh[2*j], hh[2*j+1]);
            *(__nv_bfloat162*)&Pl[rbase + b0 + 2*j] = __halves2bfloat162(ll[2*j], ll[2*j+1]);
        }
    }
    if (b1 < tile_kend) {
#pragma unroll
        for (int j = 0; j < 2; j++) {
            *(__nv_bfloat162*)&Ph[rbase + b1 + 2*j] = __halves2bfloat162(hh[4+2*j], hh[5+2*j]);
            *(__nv_bfloat162*)&Pl[rbase + b1 + 2*j] = __halves2bfloat162(ll[4+2*j], ll[5+2*j]);
        }
    }
}

// ---------------------------------------------------------------------------
// av_mma: A[q,hd] = Ph*Vh + Pl*Vh + Ph*Vl; causal chunk bound.
// Writes A in [hi|lo]-interleaved layout for the Wo GEMM.
// ---------------------------------------------------------------------------
#define AV_SMEM 98304

__global__ __launch_bounds__(256) void av_mma(
    const __nv_bfloat16* __restrict__ Ph, const __nv_bfloat16* __restrict__ Pl,
    const __nv_bfloat16* __restrict__ Vth, const __nv_bfloat16* __restrict__ Vtl,
    __nv_bfloat16* __restrict__ Acat)
{
    const int qt = blockIdx.x, bh = blockIdx.y;
    extern __shared__ __align__(1024) char smem[];
    const int tid = threadIdx.x;
    const int wid = tid >> 5, lane = tid & 31;
    const int warp_m = wid & 3;
    const int warp_n = wid >> 2;
    const uint32_t sb = smem_u32(smem);
    const int q0 = qt * 128;

    const __nv_bfloat16* Phb = Ph + (size_t)bh * S_LEN * S_LEN;
    const __nv_bfloat16* Plb = Pl + (size_t)bh * S_LEN * S_LEN;
    const __nv_bfloat16* Vhb = Vth + (size_t)bh * HD * S_LEN;
    const __nv_bfloat16* Vlb = Vtl + (size_t)bh * HD * S_LEN;

    const int ls = tid & 7;
    const int lr = tid >> 3;
    const int nch = (q0 + 128) / 64;

#define AV_LOAD(chunk, stage) do {                                             \
        uint32_t base = sb + (stage) * 49152;                                  \
        size_t kb = (size_t)(chunk) * 64 + ls * 8;                             \
        _Pragma("unroll")                                                      \
        for (int i_ = 0; i_ < 4; i_++) {                                       \
            int r_ = lr + 32 * i_;                                             \
            uint32_t off = SW128(r_ * 128 + ls * 16);                          \
            CP16(base + off,         &Phb[(size_t)(q0 + r_) * S_LEN + kb]);    \
            CP16(base + 16384 + off, &Plb[(size_t)(q0 + r_) * S_LEN + kb]);    \
        }                                                                      \
        _Pragma("unroll")                                                      \
        for (int i_ = 0; i_ < 2; i_++) {                                       \
            int r_ = lr + 32 * i_;                                             \
            uint32_t off = SW128(r_ * 128 + ls * 16);                          \
            CP16(base + 32768 + off, &Vhb[(size_t)r_ * S_LEN + kb]);           \
            CP16(base + 40960 + off, &Vlb[(size_t)r_ * S_LEN + kb]);           \
        }                                                                      \
        CP_COMMIT();                                                           \
    } while (0)

    float acc[2][4][4] = {};
    AV_LOAD(0, 0);
    for (int c = 0; c < nch; c++) {
        const int st = c & 1;
        if (c + 1 < nch) {
            AV_LOAD(c + 1, st ^ 1);
            asm volatile("cp.async.wait_group 1;");
        } else {
            asm volatile("cp.async.wait_group 0;");
        }
        __syncthreads();
        const uint32_t base = sb + st * 49152;
#pragma unroll
        for (int ks = 0; ks < 4; ks++) {
            uint32_t ah[2][4], al[2][4];
#pragma unroll
            for (int mt = 0; mt < 2; mt++) {
                int row = warp_m * 32 + mt * 16 + (lane & 15);
                int seg = ks * 2 + (lane >> 4);
                uint32_t off = SW128(row * 128 + seg * 16);
                ldm_x4(ah[mt], base + off);
                ldm_x4(al[mt], base + 16384 + off);
            }
            uint32_t bh_[2][4], bl_[2][4];
#pragma unroll
            for (int h = 0; h < 2; h++) {
                int row = warp_n * 32 + h * 16 + ((lane >> 4) & 1) * 8 + (lane & 7);
                int seg = ks * 2 + ((lane >> 3) & 1);
                uint32_t off = SW128(row * 128 + seg * 16);
                ldm_x4(bh_[h], base + 32768 + off);
                ldm_x4(bl_[h], base + 40960 + off);
            }
#pragma unroll
            for (int mt = 0; mt < 2; mt++)
#pragma unroll
                for (int nt = 0; nt < 4; nt++) {
                    uint32_t vh0 = bh_[nt >> 1][(nt & 1) * 2];
                    uint32_t vh1 = bh_[nt >> 1][(nt & 1) * 2 + 1];
                    uint32_t vl0 = bl_[nt >> 1][(nt & 1) * 2];
                    uint32_t vl1 = bl_[nt >> 1][(nt & 1) * 2 + 1];
                    mma_bf16(acc[mt][nt], ah[mt], vh0, vh1);
                    mma_bf16(acc[mt][nt], al[mt], vh0, vh1);
                    mma_bf16(acc[mt][nt], ah[mt], vl0, vl1);
                }
        }
        __syncthreads();
    }
#undef AV_LOAD

    // epilogue: write A in [hi|lo]-interleaved layout (chunked by 32)
    const int bb = bh / NH, h = bh % NH;
    const int mrow = lane >> 2;
    const int ncol = 2 * (lane & 3);
#pragma unroll
    for (int mt = 0; mt < 2; mt++)
#pragma unroll
        for (int nt = 0; nt < 4; nt++) {
            int hd = warp_n * 32 + nt * 8 + ncol;
            int cc = h * HD + hd;
            int ch = cc >> 5, p = cc & 31;
#pragma unroll
            for (int half = 0; half < 2; half++) {
                int s = q0 + warp_m * 32 + mt * 16 + mrow + half * 8;
                float v0 = acc[mt][nt][half * 2];
                float v1 = acc[mt][nt][half * 2 + 1];
                __nv_bfloat16 h0 = __float2bfloat16(v0);
                __nv_bfloat16 h1 = __float2bfloat16(v1);
                __nv_bfloat16 l0 = __float2bfloat16(v0 - __bfloat162float(h0));
                __nv_bfloat16 l1 = __float2bfloat16(v1 - __bfloat162float(h1));
                size_t base = ((size_t)(bb * S_LEN + s)) * KC2 + ch * 64 + p;
                *(__nv_bfloat162*)&Acat[base]      = __halves2bfloat162(h0, h1);
                *(__nv_bfloat162*)&Acat[base + 32] = __halves2bfloat162(l0, l1);
            }
        }
}

// ---------------------------------------------------------------------------
extern "C" void kernel_launch(void* const* d_in, const int* in_sizes, int n_in,
                              void* d_out, int out_size)
{
    const float* X  = (const float*)d_in[0];
    const float* Wq = (const float*)d_in[1];
    const float* bq = (const float*)d_in[2];
    const float* Wk = (const float*)d_in[3];
    const float* bk = (const float*)d_in[4];
    const float* Wv = (const float*)d_in[5];
    const float* bv = (const float*)d_in[6];
    const float* Wo = (const float*)d_in[7];
    const float* bo = (const float*)d_in[8];

    float* out  = (float*)d_out;
    float* attn = out + (size_t)MROWS * DM;

    __nv_bfloat16 *gXc, *gAc, *gWq, *gWk, *gWv, *gWo;
    __nv_bfloat16 *gQc, *gKc, *gVh, *gVl, *gPh, *gPl;
    cudaGetSymbolAddress((void**)&gXc, g_Xcat);
    cudaGetSymbolAddress((void**)&gAc, g_Acat);
    cudaGetSymbolAddress((void**)&gWq, g_Wqc);
    cudaGetSymbolAddress((void**)&gWk, g_Wkc);
    cudaGetSymbolAddress((void**)&gWv, g_Wvc);
    cudaGetSymbolAddress((void**)&gWo, g_Woc);
    cudaGetSymbolAddress((void**)&gQc, g_Qc);
    cudaGetSymbolAddress((void**)&gKc, g_Kc);
    cudaGetSymbolAddress((void**)&gVh, g_Vth);
    cudaGetSymbolAddress((void**)&gVl, g_Vtl);
    cudaGetSymbolAddress((void**)&gPh, g_Ph);
    cudaGetSymbolAddress((void**)&gPl, g_Pl);

    static cudaStream_t s1, s2, s3;
    static cudaEvent_t evRoot, evX, ev1, ev2, ev3;
    static int init_done = 0;
    if (!init_done) {
        cudaFuncSetAttribute(gemm_mma, cudaFuncAttributeMaxDynamicSharedMemorySize, GEMM_SMEM);
        cudaFuncSetAttribute(scores_mma, cudaFuncAttributeMaxDynamicSharedMemorySize, SC_SMEM);
        cudaFuncSetAttribute(av_mma, cudaFuncAttributeMaxDynamicSharedMemorySize, AV_SMEM);
        cudaStreamCreateWithFlags(&s1, cudaStreamNonBlocking);
        cudaStreamCreateWithFlags(&s2, cudaStreamNonBlocking);
        cudaStreamCreateWithFlags(&s3, cudaStreamNonBlocking);
        cudaEventCreateWithFlags(&evRoot, cudaEventDisableTiming);
        cudaEventCreateWithFlags(&evX, cudaEventDisableTiming);
        cudaEventCreateWithFlags(&ev1, cudaEventDisableTiming);
        cudaEventCreateWithFlags(&ev2, cudaEventDisableTiming);
        cudaEventCreateWithFlags(&ev3, cudaEventDisableTiming);
        init_done = 1;
    }

    dim3 blk(256);
    dim3 ggemm(DM / 128, MROWS / 128);

    cudaEventRecord(evRoot, 0);
    cudaStreamWaitEvent(s1, evRoot, 0);
    cudaStreamWaitEvent(s2, evRoot, 0);
    cudaStreamWaitEvent(s3, evRoot, 0);

    convert_cat<<<1024, blk, 0, 0>>>(X, gXc, MROWS);
    cudaEventRecord(evX, 0);
    convert_cat<<<512, blk, 0, 0>>>(Wo, gWo, DM);

    convert_cat<<<512, blk, 0, s1>>>(Wq, gWq, DM);
    cudaStreamWaitEvent(s1, evX, 0);
    gemm_mma<<<ggemm, blk, GEMM_SMEM, s1>>>(gXc, gWq, bq, nullptr, gQc, nullptr, 1);
    cudaEventRecord(ev1, s1);

    convert_cat<<<512, blk, 0, s2>>>(Wk, gWk, DM);
    cudaStreamWaitEvent(s2, evX, 0);
    gemm_mma<<<ggemm, blk, GEMM_SMEM, s2>>>(gXc, gWk, bk, nullptr, gKc, nullptr, 1);
    cudaEventRecord(ev2, s2);

    convert_cat<<<512, blk, 0, s3>>>(Wv, gWv, DM);
    cudaStreamWaitEvent(s3, evX, 0);
    gemm_mma<<<ggemm, blk, GEMM_SMEM, s3>>>(gXc, gWv, bv, nullptr, gVh, gVl, 3);
    cudaEventRecord(ev3, s3);

    cudaStreamWaitEvent(0, ev1, 0);
    cudaStreamWaitEvent(0, ev2, 0);
    dim3 gsc(S_LEN / 128, S_LEN / 128, BHN);
    scores_mma<<<gsc, blk, SC_SMEM, 0>>>(gQc, gKc, attn);

    dim3 gsm(S_LEN, BHN);
    softmax_kernel<<<gsm, blk, 0, 0>>>(attn, gPh, gPl);

    cudaStreamWaitEvent(0, ev3, 0);
    dim3 gav(S_LEN / 128, BHN);
    av_mma<<<gav, blk, AV_SMEM, 0>>>(gPh, gPl, gVh, gVl, gAc);

    gemm_mma<<<ggemm, blk, GEMM_SMEM, 0>>>(gAc, gWo, bo, out, nullptr, nullptr, 0);
}